// round 1
// baseline (speedup 1.0000x reference)
#include <cuda_runtime.h>

// ---------------- problem constants ----------------
#define BSZ   16
#define SEQ   1024
#define DIM   768
#define NH    12
#define HDIM  64
#define PLEN  16
#define KEYS  (PLEN + SEQ)       // 1040
#define FFD   (4 * DIM)          // 3072
#define ROWS  (BSZ * SEQ)        // 16384

// ---------------- scratch (device globals: no alloc allowed) ----------------
__device__ float g_h   [(size_t)ROWS * DIM];        // LN output (reused for ln1 and ln2)
__device__ float g_qkv [(size_t)ROWS * 3 * DIM];    // [B,N,3,H,HD]
__device__ float g_attn[(size_t)ROWS * DIM];        // attention out [B,N,H,HD]
__device__ float g_xr  [(size_t)ROWS * DIM];        // residual 1 (x + attn proj)
__device__ float g_ff  [(size_t)ROWS * FFD];        // fc1 output

// ---------------- LayerNorm ----------------
__global__ void ln_kernel(const float* __restrict__ x, const float* __restrict__ g,
                          const float* __restrict__ b, float* __restrict__ out) {
    int row = blockIdx.x;
    const float* xr = x + (size_t)row * DIM;
    float* orow = out + (size_t)row * DIM;
    int tid = threadIdx.x;

    float s = 0.f, ss = 0.f;
    for (int i = tid; i < DIM; i += 256) { float v = xr[i]; s += v; ss += v * v; }
    __shared__ float red0[8], red1[8];
    #pragma unroll
    for (int o = 16; o > 0; o >>= 1) {
        s  += __shfl_xor_sync(0xffffffffu, s, o);
        ss += __shfl_xor_sync(0xffffffffu, ss, o);
    }
    if ((tid & 31) == 0) { red0[tid >> 5] = s; red1[tid >> 5] = ss; }
    __syncthreads();
    float st = 0.f, sst = 0.f;
    #pragma unroll
    for (int i = 0; i < 8; i++) { st += red0[i]; sst += red1[i]; }
    float mean = st * (1.f / DIM);
    float var  = sst * (1.f / DIM) - mean * mean;
    float rstd = rsqrtf(var + 1e-5f);
    for (int i = tid; i < DIM; i += 256)
        orow[i] = (xr[i] - mean) * rstd * g[i] + b[i];
}

// ---------------- generic GEMM: C[M,N] = A[M,K] @ W[N,K]^T + bias (+gelu) (+resid) --------
// 128x128x8 tile, 256 threads, 8x8 per-thread micro-tile with 4+4 split mapping.
// All dims used here are divisible by 128 (M,N) and 8 (K) -> no bounds checks.
__global__ void __launch_bounds__(256, 2)
gemm_kernel(const float* __restrict__ A, const float* __restrict__ W,
            const float* __restrict__ bias, const float* __restrict__ resid,
            float* __restrict__ C, int M, int N, int K, int act) {
    __shared__ float As[8][128];
    __shared__ float Ws[8][128];
    int bm = blockIdx.y, bn = blockIdx.x;
    int tid = threadIdx.x;
    int tx = tid & 15, ty = tid >> 4;
    int lrow = tid >> 1;
    int lcol = (tid & 1) * 4;

    const float* Ap = A + (size_t)(bm * 128 + lrow) * K + lcol;
    const float* Wp = W + (size_t)(bn * 128 + lrow) * K + lcol;

    float acc[8][8] = {};

    for (int k0 = 0; k0 < K; k0 += 8) {
        float4 av = *(const float4*)(Ap + k0);
        float4 wv = *(const float4*)(Wp + k0);
        __syncthreads();
        As[lcol + 0][lrow] = av.x; As[lcol + 1][lrow] = av.y;
        As[lcol + 2][lrow] = av.z; As[lcol + 3][lrow] = av.w;
        Ws[lcol + 0][lrow] = wv.x; Ws[lcol + 1][lrow] = wv.y;
        Ws[lcol + 2][lrow] = wv.z; Ws[lcol + 3][lrow] = wv.w;
        __syncthreads();
        #pragma unroll
        for (int k = 0; k < 8; k++) {
            float a[8], bb[8];
            *(float4*)(a)      = *(const float4*)&As[k][ty * 4];
            *(float4*)(a + 4)  = *(const float4*)&As[k][64 + ty * 4];
            *(float4*)(bb)     = *(const float4*)&Ws[k][tx * 4];
            *(float4*)(bb + 4) = *(const float4*)&Ws[k][64 + tx * 4];
            #pragma unroll
            for (int i = 0; i < 8; i++)
                #pragma unroll
                for (int j = 0; j < 8; j++)
                    acc[i][j] += a[i] * bb[j];
        }
    }

    #pragma unroll
    for (int i = 0; i < 8; i++) {
        int row = bm * 128 + (i < 4 ? ty * 4 + i : 64 + ty * 4 + (i - 4));
        #pragma unroll
        for (int jg = 0; jg < 2; jg++) {
            int col = bn * 128 + jg * 64 + tx * 4;
            float4 r;
            float* rp = (float*)&r;
            #pragma unroll
            for (int j = 0; j < 4; j++) {
                float v = acc[i][jg * 4 + j] + bias[col + j];
                if (act) v = v * (1.f / (1.f + __expf(-1.702f * v)));  // QuickGELU
                rp[j] = v;
            }
            if (resid) {
                float4 rs = *(const float4*)(resid + (size_t)row * N + col);
                r.x += rs.x; r.y += rs.y; r.z += rs.z; r.w += rs.w;
            }
            *(float4*)(C + (size_t)row * N + col) = r;
        }
    }
}

// ---------------- fused attention (flash-style, online softmax) ----------------
// grid: (SEQ/64, NH, BSZ), block 256 threads. 64-q-row tile, 64-key tiles (17 tiles, last=16).
// smem: Qt[d][q] 64x64, Kt[d][key] 64x64, Vs[key][d] 64x68, St[key][q] 64x68, m/l/alpha 64 each.
#define ATT_SMEM_FLOATS (64*64 + 64*64 + 64*68 + 64*68 + 3*64)
#define ATT_SMEM_BYTES  (ATT_SMEM_FLOATS * 4)

__global__ void attn_kernel(const float* __restrict__ qkv, const float* __restrict__ prompt,
                            float* __restrict__ out) {
    extern __shared__ float sm[];
    float* Qt   = sm;                       // [64][64] d-major: Qt[d*64+q] (pre-scaled)
    float* Kt   = Qt + 64 * 64;             // [64][64] d-major: Kt[d*64+key]
    float* Vs   = Kt + 64 * 64;             // [64][68] key-major: Vs[key*68+d]
    float* St   = Vs + 64 * 68;             // [64][68] key-major: St[key*68+q]
    float* mrow = St + 64 * 68;             // [64]
    float* lrow = mrow + 64;                // [64]
    float* arow = lrow + 64;                // [64]

    int qt = blockIdx.x, h = blockIdx.y, b = blockIdx.z;
    int tid = threadIdx.x;
    int tx = tid & 15, ty = tid >> 4;

    // --- load Q tile (scaled by 1/sqrt(HD) = 0.125) into Qt[d][q] ---
    {
        int q = tid & 63, ch = tid >> 6;    // 64 q x 4 chunks of 16 d
        int n = qt * 64 + q;
        const float* src = qkv + (size_t)(b * SEQ + n) * (3 * DIM) + (0 * NH + h) * HDIM + ch * 16;
        #pragma unroll
        for (int ii = 0; ii < 4; ii++) {
            float4 v = *(const float4*)(src + ii * 4);
            int d = ch * 16 + ii * 4;
            Qt[(d + 0) * 64 + q] = v.x * 0.125f;
            Qt[(d + 1) * 64 + q] = v.y * 0.125f;
            Qt[(d + 2) * 64 + q] = v.z * 0.125f;
            Qt[(d + 3) * 64 + q] = v.w * 0.125f;
        }
    }
    if (tid < 64) { mrow[tid] = -1e30f; lrow[tid] = 0.f; }

    float o[4][4] = {};                     // [qi][dj]

    for (int kt = 0; kt < 17; kt++) {
        __syncthreads();                    // prev PV / Q-load complete before overwriting tiles
        // --- K tile -> Kt[d][key] ---
        {
            int key = tid & 63, ch = tid >> 6;
            int kg = kt * 64 + key;
            bool valid = kg < KEYS;
            const float* src = nullptr;
            if (valid) {
                if (kg < PLEN)
                    src = prompt + ((((size_t)b * 2 + 0) * PLEN + kg) * NH + h) * HDIM + ch * 16;
                else
                    src = qkv + (size_t)(b * SEQ + (kg - PLEN)) * (3 * DIM) + (1 * NH + h) * HDIM + ch * 16;
            }
            #pragma unroll
            for (int ii = 0; ii < 4; ii++) {
                float4 v = valid ? *(const float4*)(src + ii * 4) : make_float4(0.f, 0.f, 0.f, 0.f);
                int d = ch * 16 + ii * 4;
                Kt[(d + 0) * 64 + key] = v.x;
                Kt[(d + 1) * 64 + key] = v.y;
                Kt[(d + 2) * 64 + key] = v.z;
                Kt[(d + 3) * 64 + key] = v.w;
            }
        }
        // --- V tile -> Vs[key][d] (zero-filled when invalid) ---
        {
            int key = tid >> 2, part = tid & 3;
            int kg = kt * 64 + key;
            bool valid = kg < KEYS;
            const float* src = nullptr;
            if (valid) {
                if (kg < PLEN)
                    src = prompt + ((((size_t)b * 2 + 1) * PLEN + kg) * NH + h) * HDIM + part * 16;
                else
                    src = qkv + (size_t)(b * SEQ + (kg - PLEN)) * (3 * DIM) + (2 * NH + h) * HDIM + part * 16;
            }
            #pragma unroll
            for (int ii = 0; ii < 4; ii++) {
                float4 v = valid ? *(const float4*)(src + ii * 4) : make_float4(0.f, 0.f, 0.f, 0.f);
                *(float4*)&Vs[key * 68 + part * 16 + ii * 4] = v;
            }
        }
        __syncthreads();

        // --- S = Q @ K^T (per-thread 4q x 4key micro-tile) ---
        float sacc[4][4] = {};
        #pragma unroll 16
        for (int d = 0; d < 64; d++) {
            float4 a  = *(const float4*)&Qt[d * 64 + ty * 4];
            float4 bb = *(const float4*)&Kt[d * 64 + tx * 4];
            float av[4] = {a.x, a.y, a.z, a.w};
            float bv[4] = {bb.x, bb.y, bb.z, bb.w};
            #pragma unroll
            for (int i = 0; i < 4; i++)
                #pragma unroll
                for (int j = 0; j < 4; j++)
                    sacc[i][j] += av[i] * bv[j];
        }
        // store transposed St[key][q]; mask invalid keys with -1e30
        #pragma unroll
        for (int j = 0; j < 4; j++) {
            int kg = kt * 64 + tx * 4 + j;
            float4 w = (kg < KEYS)
                ? make_float4(sacc[0][j], sacc[1][j], sacc[2][j], sacc[3][j])
                : make_float4(-1e30f, -1e30f, -1e30f, -1e30f);
            *(float4*)&St[(tx * 4 + j) * 68 + ty * 4] = w;
        }
        __syncthreads();

        // --- online softmax: 4 threads per q-row, 16 keys each ---
        {
            int q = tid >> 2, part = tid & 3;
            float mt = -1e30f;
            #pragma unroll
            for (int i = 0; i < 16; i++) mt = fmaxf(mt, St[(part * 16 + i) * 68 + q]);
            mt = fmaxf(mt, __shfl_xor_sync(0xffffffffu, mt, 1));
            mt = fmaxf(mt, __shfl_xor_sync(0xffffffffu, mt, 2));
            float mold = mrow[q];
            float mnew = fmaxf(mold, mt);
            float lsum = 0.f;
            #pragma unroll
            for (int i = 0; i < 16; i++) {
                float p = __expf(St[(part * 16 + i) * 68 + q] - mnew);
                St[(part * 16 + i) * 68 + q] = p;
                lsum += p;
            }
            lsum += __shfl_xor_sync(0xffffffffu, lsum, 1);
            lsum += __shfl_xor_sync(0xffffffffu, lsum, 2);
            float alpha = __expf(mold - mnew);
            if (part == 0) {
                mrow[q] = mnew;
                lrow[q] = lrow[q] * alpha + lsum;
                arow[q] = alpha;
            }
        }
        __syncthreads();

        // --- O = O*alpha + P @ V ---
        float al[4];
        #pragma unroll
        for (int i = 0; i < 4; i++) al[i] = arow[ty * 4 + i];
        #pragma unroll
        for (int i = 0; i < 4; i++)
            #pragma unroll
            for (int j = 0; j < 4; j++)
                o[i][j] *= al[i];
        #pragma unroll 16
        for (int kk = 0; kk < 64; kk++) {
            float4 p = *(const float4*)&St[kk * 68 + ty * 4];
            float4 v = *(const float4*)&Vs[kk * 68 + tx * 4];
            float pv[4] = {p.x, p.y, p.z, p.w};
            float vv[4] = {v.x, v.y, v.z, v.w};
            #pragma unroll
            for (int i = 0; i < 4; i++)
                #pragma unroll
                for (int j = 0; j < 4; j++)
                    o[i][j] += pv[i] * vv[j];
        }
    }

    // --- finalize: divide by l, write [B,N,H,HD] ---
    #pragma unroll
    for (int i = 0; i < 4; i++) {
        float linv = 1.f / lrow[ty * 4 + i];
        int n = qt * 64 + ty * 4 + i;
        float4 w = make_float4(o[i][0] * linv, o[i][1] * linv, o[i][2] * linv, o[i][3] * linv);
        *(float4*)(out + (size_t)(b * SEQ + n) * DIM + h * HDIM + tx * 4) = w;
    }
}

// ---------------- launch ----------------
extern "C" void kernel_launch(void* const* d_in, const int* in_sizes, int n_in,
                              void* d_out, int out_size) {
    const float* x      = (const float*)d_in[0];
    const float* prompt = (const float*)d_in[1];
    const float* qkv_w  = (const float*)d_in[2];
    const float* qkv_b  = (const float*)d_in[3];
    const float* out_w  = (const float*)d_in[4];
    const float* out_b  = (const float*)d_in[5];
    const float* ln1_g  = (const float*)d_in[6];
    const float* ln1_b  = (const float*)d_in[7];
    const float* ln2_g  = (const float*)d_in[8];
    const float* ln2_b  = (const float*)d_in[9];
    const float* fc1_w  = (const float*)d_in[10];
    const float* fc1_b  = (const float*)d_in[11];
    const float* fc2_w  = (const float*)d_in[12];
    const float* fc2_b  = (const float*)d_in[13];
    float* out = (float*)d_out;

    float *h, *qkv, *attn, *xr, *ff;
    cudaGetSymbolAddress((void**)&h,    g_h);
    cudaGetSymbolAddress((void**)&qkv,  g_qkv);
    cudaGetSymbolAddress((void**)&attn, g_attn);
    cudaGetSymbolAddress((void**)&xr,   g_xr);
    cudaGetSymbolAddress((void**)&ff,   g_ff);

    cudaFuncSetAttribute(attn_kernel, cudaFuncAttributeMaxDynamicSharedMemorySize, ATT_SMEM_BYTES);

    // 1) h = LN1(x)
    ln_kernel<<<ROWS, 256>>>(x, ln1_g, ln1_b, h);
    // 2) qkv = h @ qkv_w^T + qkv_b            [16384, 2304]
    gemm_kernel<<<dim3(3 * DIM / 128, ROWS / 128), 256>>>(h, qkv_w, qkv_b, nullptr, qkv,
                                                          ROWS, 3 * DIM, DIM, 0);
    // 3) attn = softmax(Q [Kp;K]^T) [Vp;V]    [16384, 768]
    attn_kernel<<<dim3(SEQ / 64, NH, BSZ), 256, ATT_SMEM_BYTES>>>(qkv, prompt, attn);
    // 4) xr = x + attn @ out_w^T + out_b
    gemm_kernel<<<dim3(DIM / 128, ROWS / 128), 256>>>(attn, out_w, out_b, x, xr,
                                                      ROWS, DIM, DIM, 0);
    // 5) h = LN2(xr)
    ln_kernel<<<ROWS, 256>>>(xr, ln2_g, ln2_b, h);
    // 6) ff = quickgelu(h @ fc1_w^T + fc1_b)  [16384, 3072]
    gemm_kernel<<<dim3(FFD / 128, ROWS / 128), 256>>>(h, fc1_w, fc1_b, nullptr, ff,
                                                      ROWS, FFD, DIM, 1);
    // 7) out = xr + ff @ fc2_w^T + fc2_b
    gemm_kernel<<<dim3(DIM / 128, ROWS / 128), 256>>>(ff, fc2_w, fc2_b, xr, out,
                                                      ROWS, DIM, FFD, 0);
}

// round 3
// speedup vs baseline: 1.6137x; 1.6137x over previous
#include <cuda_runtime.h>
#include <cstdint>

// ---------------- problem constants ----------------
#define BSZ   16
#define SEQ   1024
#define DIM   768
#define NH    12
#define HDIM  64
#define PLEN  16
#define KEYS  (PLEN + SEQ)       // 1040
#define FFD   (4 * DIM)          // 3072
#define ROWS  (BSZ * SEQ)        // 16384

// ---------------- scratch (device globals: no alloc allowed) ----------------
__device__ float g_h   [(size_t)ROWS * DIM];
__device__ float g_qkv [(size_t)ROWS * 3 * DIM];
__device__ float g_attn[(size_t)ROWS * DIM];
__device__ float g_xr  [(size_t)ROWS * DIM];
__device__ float g_ff  [(size_t)ROWS * FFD];

// ---------------- helpers ----------------
__device__ __forceinline__ uint32_t f2tf32(float f) {
    uint32_t r;
    asm("cvt.rna.tf32.f32 %0, %1;" : "=r"(r) : "f"(f));
    return r;
}
__device__ __forceinline__ uint32_t smem_u32(const void* p) {
    uint32_t a;
    asm("{ .reg .u64 t; cvta.to.shared.u64 t, %1; cvt.u32.u64 %0, t; }" : "=r"(a) : "l"(p));
    return a;
}
__device__ __forceinline__ void cp_async16(uint32_t dst, const void* src) {
    asm volatile("cp.async.cg.shared.global [%0], [%1], 16;" :: "r"(dst), "l"(src) : "memory");
}
#define CP_COMMIT() asm volatile("cp.async.commit_group;" ::: "memory")
#define CP_WAIT(n)  asm volatile("cp.async.wait_group %0;" :: "n"(n) : "memory")

__device__ __forceinline__ void mma_tf32(float* c, const uint32_t* a, const uint32_t* b) {
    asm volatile(
        "mma.sync.aligned.m16n8k8.row.col.f32.tf32.tf32.f32 "
        "{%0,%1,%2,%3}, {%4,%5,%6,%7}, {%8,%9}, {%0,%1,%2,%3};"
        : "+f"(c[0]), "+f"(c[1]), "+f"(c[2]), "+f"(c[3])
        : "r"(a[0]), "r"(a[1]), "r"(a[2]), "r"(a[3]), "r"(b[0]), "r"(b[1]));
}

// ---------------- tf32 mma.sync GEMM: C[M,N] = A[M,K] @ W[N,K]^T + bias (+gelu) (+resid)
// 128x128 CTA tile, 8 warps of 64x32, K-chunks of 32, cp.async double buffer.
// smem per buffer per matrix: 128 rows x 36 floats (pad) = 18432 B. Total 73728 B.
#define GP        36
#define GBUF      (128 * GP)               // floats per buffer
#define GSM_A(s)  ((s) * GBUF)             // float offsets
#define GSM_B(s)  (2 * GBUF + (s) * GBUF)
#define GSM_BYTES (4 * GBUF * 4)

__global__ void __launch_bounds__(256)
mma_gemm(const float* __restrict__ A, const float* __restrict__ W,
         const float* __restrict__ bias, const float* __restrict__ resid,
         float* __restrict__ C, int M, int N, int K, int act) {
    extern __shared__ float sm[];
    int tid = threadIdx.x;
    int wid = tid >> 5, lane = tid & 31;
    int g = lane >> 2, t = lane & 3;          // mma group / thread-in-group
    int bm = blockIdx.y, bn = blockIdx.x;
    int warpm = wid & 1, warpn = wid >> 1;
    int wm0 = warpm * 64, wn0 = warpn * 32;

    // per-thread load assignment: row r (0..127), 16 floats starting at hf
    int r  = tid >> 1;
    int hf = (tid & 1) << 4;
    const float* Ap = A + (size_t)(bm * 128 + r) * K + hf;
    const float* Wp = W + (size_t)(bn * 128 + r) * K + hf;
    uint32_t smA_dst[2], smB_dst[2];
    {
        uint32_t base = smem_u32(sm);
        smA_dst[0] = base + (GSM_A(0) + r * GP + hf) * 4;
        smA_dst[1] = base + (GSM_A(1) + r * GP + hf) * 4;
        smB_dst[0] = base + (GSM_B(0) + r * GP + hf) * 4;
        smB_dst[1] = base + (GSM_B(1) + r * GP + hf) * 4;
    }

    float acc[4][4][4] = {};
    int nc = K >> 5;

    // prologue: chunk 0 -> buf 0
    #pragma unroll
    for (int i = 0; i < 4; i++) cp_async16(smA_dst[0] + i * 16, Ap + i * 4);
    #pragma unroll
    for (int i = 0; i < 4; i++) cp_async16(smB_dst[0] + i * 16, Wp + i * 4);
    CP_COMMIT();

    for (int c = 0; c < nc; c++) {
        int s = c & 1;
        if (c + 1 < nc) {
            int s2 = s ^ 1;
            const float* ap = Ap + (c + 1) * 32;
            const float* wp = Wp + (c + 1) * 32;
            #pragma unroll
            for (int i = 0; i < 4; i++) cp_async16(smA_dst[s2] + i * 16, ap + i * 4);
            #pragma unroll
            for (int i = 0; i < 4; i++) cp_async16(smB_dst[s2] + i * 16, wp + i * 4);
            CP_COMMIT();
            CP_WAIT(1);
        } else {
            CP_WAIT(0);
        }
        __syncthreads();

        const float* As_ = sm + GSM_A(s);
        const float* Bs_ = sm + GSM_B(s);
        #pragma unroll
        for (int k0 = 0; k0 < 32; k0 += 8) {
            uint32_t af[4][4], bf[4][2];
            #pragma unroll
            for (int mt = 0; mt < 4; mt++) {
                int r0 = wm0 + mt * 16 + g;
                af[mt][0] = f2tf32(As_[r0 * GP + k0 + t]);
                af[mt][1] = f2tf32(As_[(r0 + 8) * GP + k0 + t]);
                af[mt][2] = f2tf32(As_[r0 * GP + k0 + t + 4]);
                af[mt][3] = f2tf32(As_[(r0 + 8) * GP + k0 + t + 4]);
            }
            #pragma unroll
            for (int nt = 0; nt < 4; nt++) {
                int n0 = wn0 + nt * 8 + g;
                bf[nt][0] = f2tf32(Bs_[n0 * GP + k0 + t]);
                bf[nt][1] = f2tf32(Bs_[n0 * GP + k0 + t + 4]);
            }
            #pragma unroll
            for (int mt = 0; mt < 4; mt++)
                #pragma unroll
                for (int nt = 0; nt < 4; nt++)
                    mma_tf32(acc[mt][nt], af[mt], bf[nt]);
        }
        __syncthreads();
    }

    // epilogue: each thread owns rows (wm0+mt*16+g, +8), cols (wn0+nt*8+2t, +1)
    #pragma unroll
    for (int mt = 0; mt < 4; mt++) {
        #pragma unroll
        for (int half = 0; half < 2; half++) {
            int row = bm * 128 + wm0 + mt * 16 + g + half * 8;
            float* Crow = C + (size_t)row * N;
            const float* Rrow = resid ? resid + (size_t)row * N : nullptr;
            #pragma unroll
            for (int nt = 0; nt < 4; nt++) {
                int col = bn * 128 + wn0 + nt * 8 + 2 * t;
                float2 v;
                v.x = acc[mt][nt][2 * half + 0] + bias[col];
                v.y = acc[mt][nt][2 * half + 1] + bias[col + 1];
                if (act) {
                    v.x *= 1.f / (1.f + __expf(-1.702f * v.x));
                    v.y *= 1.f / (1.f + __expf(-1.702f * v.y));
                }
                if (Rrow) {
                    float2 rs = *(const float2*)(Rrow + col);
                    v.x += rs.x; v.y += rs.y;
                }
                *(float2*)(Crow + col) = v;
            }
        }
    }
}

// ---------------- LayerNorm ----------------
__global__ void ln_kernel(const float* __restrict__ x, const float* __restrict__ g,
                          const float* __restrict__ b, float* __restrict__ out) {
    int row = blockIdx.x;
    const float* xr = x + (size_t)row * DIM;
    float* orow = out + (size_t)row * DIM;
    int tid = threadIdx.x;

    float s = 0.f, ss = 0.f;
    for (int i = tid; i < DIM; i += 256) { float v = xr[i]; s += v; ss += v * v; }
    __shared__ float red0[8], red1[8];
    #pragma unroll
    for (int o = 16; o > 0; o >>= 1) {
        s  += __shfl_xor_sync(0xffffffffu, s, o);
        ss += __shfl_xor_sync(0xffffffffu, ss, o);
    }
    if ((tid & 31) == 0) { red0[tid >> 5] = s; red1[tid >> 5] = ss; }
    __syncthreads();
    float st = 0.f, sst = 0.f;
    #pragma unroll
    for (int i = 0; i < 8; i++) { st += red0[i]; sst += red1[i]; }
    float mean = st * (1.f / DIM);
    float var  = sst * (1.f / DIM) - mean * mean;
    float rstd = rsqrtf(var + 1e-5f);
    for (int i = tid; i < DIM; i += 256)
        orow[i] = (xr[i] - mean) * rstd * g[i] + b[i];
}

// ---------------- fused attention (flash-style, fp32 SIMT) ----------------
#define ATT_SMEM_FLOATS (64*64 + 64*64 + 64*68 + 64*68 + 3*64)
#define ATT_SMEM_BYTES  (ATT_SMEM_FLOATS * 4)

__global__ void attn_kernel(const float* __restrict__ qkv, const float* __restrict__ prompt,
                            float* __restrict__ out) {
    extern __shared__ float smf[];
    float* Qt   = smf;
    float* Kt   = Qt + 64 * 64;
    float* Vs   = Kt + 64 * 64;
    float* St   = Vs + 64 * 68;
    float* mrow = St + 64 * 68;
    float* lrow = mrow + 64;
    float* arow = lrow + 64;

    int qt = blockIdx.x, h = blockIdx.y, b = blockIdx.z;
    int tid = threadIdx.x;
    int tx = tid & 15, ty = tid >> 4;

    {
        int q = tid & 63, ch = tid >> 6;
        int n = qt * 64 + q;
        const float* src = qkv + (size_t)(b * SEQ + n) * (3 * DIM) + (0 * NH + h) * HDIM + ch * 16;
        #pragma unroll
        for (int ii = 0; ii < 4; ii++) {
            float4 v = *(const float4*)(src + ii * 4);
            int d = ch * 16 + ii * 4;
            Qt[(d + 0) * 64 + q] = v.x * 0.125f;
            Qt[(d + 1) * 64 + q] = v.y * 0.125f;
            Qt[(d + 2) * 64 + q] = v.z * 0.125f;
            Qt[(d + 3) * 64 + q] = v.w * 0.125f;
        }
    }
    if (tid < 64) { mrow[tid] = -1e30f; lrow[tid] = 0.f; }

    float o[4][4] = {};

    for (int kt = 0; kt < 17; kt++) {
        __syncthreads();
        {
            int key = tid & 63, ch = tid >> 6;
            int kg = kt * 64 + key;
            bool valid = kg < KEYS;
            const float* src = nullptr;
            if (valid) {
                if (kg < PLEN)
                    src = prompt + ((((size_t)b * 2 + 0) * PLEN + kg) * NH + h) * HDIM + ch * 16;
                else
                    src = qkv + (size_t)(b * SEQ + (kg - PLEN)) * (3 * DIM) + (1 * NH + h) * HDIM + ch * 16;
            }
            #pragma unroll
            for (int ii = 0; ii < 4; ii++) {
                float4 v = valid ? *(const float4*)(src + ii * 4) : make_float4(0.f, 0.f, 0.f, 0.f);
                int d = ch * 16 + ii * 4;
                Kt[(d + 0) * 64 + key] = v.x;
                Kt[(d + 1) * 64 + key] = v.y;
                Kt[(d + 2) * 64 + key] = v.z;
                Kt[(d + 3) * 64 + key] = v.w;
            }
        }
        {
            int key = tid >> 2, part = tid & 3;
            int kg = kt * 64 + key;
            bool valid = kg < KEYS;
            const float* src = nullptr;
            if (valid) {
                if (kg < PLEN)
                    src = prompt + ((((size_t)b * 2 + 1) * PLEN + kg) * NH + h) * HDIM + part * 16;
                else
                    src = qkv + (size_t)(b * SEQ + (kg - PLEN)) * (3 * DIM) + (2 * NH + h) * HDIM + part * 16;
            }
            #pragma unroll
            for (int ii = 0; ii < 4; ii++) {
                float4 v = valid ? *(const float4*)(src + ii * 4) : make_float4(0.f, 0.f, 0.f, 0.f);
                *(float4*)&Vs[key * 68 + part * 16 + ii * 4] = v;
            }
        }
        __syncthreads();

        float sacc[4][4] = {};
        #pragma unroll 16
        for (int d = 0; d < 64; d++) {
            float4 a  = *(const float4*)&Qt[d * 64 + ty * 4];
            float4 bb = *(const float4*)&Kt[d * 64 + tx * 4];
            float av[4] = {a.x, a.y, a.z, a.w};
            float bv[4] = {bb.x, bb.y, bb.z, bb.w};
            #pragma unroll
            for (int i = 0; i < 4; i++)
                #pragma unroll
                for (int j = 0; j < 4; j++)
                    sacc[i][j] += av[i] * bv[j];
        }
        #pragma unroll
        for (int j = 0; j < 4; j++) {
            int kg = kt * 64 + tx * 4 + j;
            float4 w = (kg < KEYS)
                ? make_float4(sacc[0][j], sacc[1][j], sacc[2][j], sacc[3][j])
                : make_float4(-1e30f, -1e30f, -1e30f, -1e30f);
            *(float4*)&St[(tx * 4 + j) * 68 + ty * 4] = w;
        }
        __syncthreads();

        {
            int q = tid >> 2, part = tid & 3;
            float mt = -1e30f;
            #pragma unroll
            for (int i = 0; i < 16; i++) mt = fmaxf(mt, St[(part * 16 + i) * 68 + q]);
            mt = fmaxf(mt, __shfl_xor_sync(0xffffffffu, mt, 1));
            mt = fmaxf(mt, __shfl_xor_sync(0xffffffffu, mt, 2));
            float mold = mrow[q];
            float mnew = fmaxf(mold, mt);
            float lsum = 0.f;
            #pragma unroll
            for (int i = 0; i < 16; i++) {
                float p = __expf(St[(part * 16 + i) * 68 + q] - mnew);
                St[(part * 16 + i) * 68 + q] = p;
                lsum += p;
            }
            lsum += __shfl_xor_sync(0xffffffffu, lsum, 1);
            lsum += __shfl_xor_sync(0xffffffffu, lsum, 2);
            float alpha = __expf(mold - mnew);
            if (part == 0) {
                mrow[q] = mnew;
                lrow[q] = lrow[q] * alpha + lsum;
                arow[q] = alpha;
            }
        }
        __syncthreads();

        float al[4];
        #pragma unroll
        for (int i = 0; i < 4; i++) al[i] = arow[ty * 4 + i];
        #pragma unroll
        for (int i = 0; i < 4; i++)
            #pragma unroll
            for (int j = 0; j < 4; j++)
                o[i][j] *= al[i];
        #pragma unroll 16
        for (int kk = 0; kk < 64; kk++) {
            float4 p = *(const float4*)&St[kk * 68 + ty * 4];
            float4 v = *(const float4*)&Vs[kk * 68 + tx * 4];
            float pv[4] = {p.x, p.y, p.z, p.w};
            float vv[4] = {v.x, v.y, v.z, v.w};
            #pragma unroll
            for (int i = 0; i < 4; i++)
                #pragma unroll
                for (int j = 0; j < 4; j++)
                    o[i][j] += pv[i] * vv[j];
        }
    }

    #pragma unroll
    for (int i = 0; i < 4; i++) {
        float linv = 1.f / lrow[ty * 4 + i];
        int n = qt * 64 + ty * 4 + i;
        float4 w = make_float4(o[i][0] * linv, o[i][1] * linv, o[i][2] * linv, o[i][3] * linv);
        *(float4*)(out + (size_t)(b * SEQ + n) * DIM + h * HDIM + tx * 4) = w;
    }
}

// ---------------- launch ----------------
extern "C" void kernel_launch(void* const* d_in, const int* in_sizes, int n_in,
                              void* d_out, int out_size) {
    const float* x      = (const float*)d_in[0];
    const float* prompt = (const float*)d_in[1];
    const float* qkv_w  = (const float*)d_in[2];
    const float* qkv_b  = (const float*)d_in[3];
    const float* out_w  = (const float*)d_in[4];
    const float* out_b  = (const float*)d_in[5];
    const float* ln1_g  = (const float*)d_in[6];
    const float* ln1_b  = (const float*)d_in[7];
    const float* ln2_g  = (const float*)d_in[8];
    const float* ln2_b  = (const float*)d_in[9];
    const float* fc1_w  = (const float*)d_in[10];
    const float* fc1_b  = (const float*)d_in[11];
    const float* fc2_w  = (const float*)d_in[12];
    const float* fc2_b  = (const float*)d_in[13];
    float* out = (float*)d_out;

    float *h, *qkv, *attn, *xr, *ff;
    cudaGetSymbolAddress((void**)&h,    g_h);
    cudaGetSymbolAddress((void**)&qkv,  g_qkv);
    cudaGetSymbolAddress((void**)&attn, g_attn);
    cudaGetSymbolAddress((void**)&xr,   g_xr);
    cudaGetSymbolAddress((void**)&ff,   g_ff);

    cudaFuncSetAttribute(attn_kernel, cudaFuncAttributeMaxDynamicSharedMemorySize, ATT_SMEM_BYTES);
    cudaFuncSetAttribute(mma_gemm, cudaFuncAttributeMaxDynamicSharedMemorySize, GSM_BYTES);

    // 1) h = LN1(x)
    ln_kernel<<<ROWS, 256>>>(x, ln1_g, ln1_b, h);
    // 2) qkv = h @ qkv_w^T + qkv_b
    mma_gemm<<<dim3(3 * DIM / 128, ROWS / 128), 256, GSM_BYTES>>>(h, qkv_w, qkv_b, nullptr, qkv,
                                                                  ROWS, 3 * DIM, DIM, 0);
    // 3) attention
    attn_kernel<<<dim3(SEQ / 64, NH, BSZ), 256, ATT_SMEM_BYTES>>>(qkv, prompt, attn);
    // 4) xr = x + attn @ out_w^T + out_b
    mma_gemm<<<dim3(DIM / 128, ROWS / 128), 256, GSM_BYTES>>>(attn, out_w, out_b, x, xr,
                                                              ROWS, DIM, DIM, 0);
    // 5) h = LN2(xr)
    ln_kernel<<<ROWS, 256>>>(xr, ln2_g, ln2_b, h);
    // 6) ff = quickgelu(h @ fc1_w^T + fc1_b)
    mma_gemm<<<dim3(FFD / 128, ROWS / 128), 256, GSM_BYTES>>>(h, fc1_w, fc1_b, nullptr, ff,
                                                              ROWS, FFD, DIM, 1);
    // 7) out = xr + ff @ fc2_w^T + fc2_b
    mma_gemm<<<dim3(DIM / 128, ROWS / 128), 256, GSM_BYTES>>>(ff, fc2_w, fc2_b, xr, out,
                                                              ROWS, DIM, FFD, 0);
}

// round 4
// speedup vs baseline: 1.6319x; 1.0113x over previous
#include <cuda_runtime.h>
#include <cstdint>

// ---------------- problem constants ----------------
#define BSZ   16
#define SEQ   1024
#define DIM   768
#define NH    12
#define HDIM  64
#define PLEN  16
#define KEYS  (PLEN + SEQ)       // 1040
#define FFD   (4 * DIM)          // 3072
#define ROWS  (BSZ * SEQ)        // 16384

// within-8 k permutation so mma pair (t, t+4) is adjacent
#define PCOL(k) (((k) & ~7) | ((((k) & 3) << 1) | (((k) >> 2) & 1)))

// ---------------- scratch (device globals: no alloc allowed) ----------------
__device__ uint32_t g_h   [(size_t)ROWS * DIM];     // LN out, tf32-perm
__device__ float    g_qkv [(size_t)ROWS * 3 * DIM]; // fp32
__device__ uint32_t g_attn[(size_t)ROWS * DIM];     // attn out, tf32-perm
__device__ float    g_xr  [(size_t)ROWS * DIM];     // residual 1, fp32
__device__ uint32_t g_ff  [(size_t)ROWS * FFD];     // gelu out, tf32-perm
__device__ uint32_t g_wq  [(size_t)3 * DIM * DIM];  // weights tf32-perm
__device__ uint32_t g_wo  [(size_t)DIM * DIM];
__device__ uint32_t g_wf1 [(size_t)FFD * DIM];
__device__ uint32_t g_wf2 [(size_t)DIM * FFD];

// ---------------- helpers ----------------
__device__ __forceinline__ uint32_t f2tf32(float f) {
    uint32_t r;
    asm("cvt.rna.tf32.f32 %0, %1;" : "=r"(r) : "f"(f));
    return r;
}
__device__ __forceinline__ uint32_t smem_u32(const void* p) {
    uint32_t a;
    asm("{ .reg .u64 t; cvta.to.shared.u64 t, %1; cvt.u32.u64 %0, t; }" : "=r"(a) : "l"(p));
    return a;
}
__device__ __forceinline__ void cp_async16(uint32_t dst, const void* src) {
    asm volatile("cp.async.cg.shared.global [%0], [%1], 16;" :: "r"(dst), "l"(src) : "memory");
}
#define CP_COMMIT() asm volatile("cp.async.commit_group;" ::: "memory")
#define CP_WAIT(n)  asm volatile("cp.async.wait_group %0;" :: "n"(n) : "memory")

__device__ __forceinline__ void mma_tf32(float* c, const uint32_t* a, const uint32_t* b) {
    asm volatile(
        "mma.sync.aligned.m16n8k8.row.col.f32.tf32.tf32.f32 "
        "{%0,%1,%2,%3}, {%4,%5,%6,%7}, {%8,%9}, {%0,%1,%2,%3};"
        : "+f"(c[0]), "+f"(c[1]), "+f"(c[2]), "+f"(c[3])
        : "r"(a[0]), "r"(a[1]), "r"(a[2]), "r"(a[3]), "r"(b[0]), "r"(b[1]));
}

// ---------------- weight convert: fp32 -> tf32, permuted k within rows of length K ----
__global__ void cvt_w(const float* __restrict__ in, uint32_t* __restrict__ out, int total, int K) {
    int idx = blockIdx.x * 256 + threadIdx.x;
    if (idx >= total) return;
    int row = idx / K, k = idx - row * K;
    out[(size_t)row * K + PCOL(k)] = f2tf32(in[idx]);
}

// ---------------- tf32 mma.sync GEMM on pre-permuted tf32 operands ----------------
// C = A @ W^T + bias, modes: 0 = fp32 out, 1 = gelu + tf32-perm out, 2 = resid + fp32 out
// 128x128 CTA tile, 8 warps of 64x32, K-chunks of 32, cp.async double buffer.
// smem rows padded to 40 u32.
#define GP        40
#define GBUF      (128 * GP)
#define GSM_A(s)  ((s) * GBUF)
#define GSM_B(s)  (2 * GBUF + (s) * GBUF)
#define GSM_BYTES (4 * GBUF * 4)

__global__ void __launch_bounds__(256, 2)
mma_gemm(const uint32_t* __restrict__ A, const uint32_t* __restrict__ W,
         const float* __restrict__ bias, const float* __restrict__ resid,
         void* __restrict__ Cout, int M, int N, int K, int mode) {
    extern __shared__ uint32_t smu[];
    int tid = threadIdx.x;
    int wid = tid >> 5, lane = tid & 31;
    int g = lane >> 2, t = lane & 3;
    int bm = blockIdx.y, bn = blockIdx.x;
    int wm0 = (wid & 1) * 64, wn0 = (wid >> 1) * 32;

    int r  = tid >> 1;
    int hf = (tid & 1) << 4;
    const uint32_t* Ap = A + (size_t)(bm * 128 + r) * K + hf;
    const uint32_t* Wp = W + (size_t)(bn * 128 + r) * K + hf;
    uint32_t smA_dst[2], smB_dst[2];
    {
        uint32_t base = smem_u32(smu);
        smA_dst[0] = base + (GSM_A(0) + r * GP + hf) * 4;
        smA_dst[1] = base + (GSM_A(1) + r * GP + hf) * 4;
        smB_dst[0] = base + (GSM_B(0) + r * GP + hf) * 4;
        smB_dst[1] = base + (GSM_B(1) + r * GP + hf) * 4;
    }

    float acc[4][4][4] = {};
    int nc = K >> 5;

    #pragma unroll
    for (int i = 0; i < 4; i++) cp_async16(smA_dst[0] + i * 16, Ap + i * 4);
    #pragma unroll
    for (int i = 0; i < 4; i++) cp_async16(smB_dst[0] + i * 16, Wp + i * 4);
    CP_COMMIT();

    for (int c = 0; c < nc; c++) {
        int s = c & 1;
        if (c + 1 < nc) {
            int s2 = s ^ 1;
            const uint32_t* ap = Ap + (c + 1) * 32;
            const uint32_t* wp = Wp + (c + 1) * 32;
            #pragma unroll
            for (int i = 0; i < 4; i++) cp_async16(smA_dst[s2] + i * 16, ap + i * 4);
            #pragma unroll
            for (int i = 0; i < 4; i++) cp_async16(smB_dst[s2] + i * 16, wp + i * 4);
            CP_COMMIT();
            CP_WAIT(1);
        } else {
            CP_WAIT(0);
        }
        __syncthreads();

        const uint32_t* As_ = smu + GSM_A(s);
        const uint32_t* Bs_ = smu + GSM_B(s);
        #pragma unroll
        for (int k0 = 0; k0 < 32; k0 += 8) {
            uint32_t af[4][4], bf[4][2];
            #pragma unroll
            for (int mt = 0; mt < 4; mt++) {
                int r0 = wm0 + mt * 16 + g;
                uint2 lo = *(const uint2*)(As_ + r0 * GP + k0 + 2 * t);
                uint2 hi = *(const uint2*)(As_ + (r0 + 8) * GP + k0 + 2 * t);
                af[mt][0] = lo.x; af[mt][2] = lo.y;
                af[mt][1] = hi.x; af[mt][3] = hi.y;
            }
            #pragma unroll
            for (int nt = 0; nt < 4; nt++) {
                int n0 = wn0 + nt * 8 + g;
                uint2 bv = *(const uint2*)(Bs_ + n0 * GP + k0 + 2 * t);
                bf[nt][0] = bv.x; bf[nt][1] = bv.y;
            }
            #pragma unroll
            for (int mt = 0; mt < 4; mt++)
                #pragma unroll
                for (int nt = 0; nt < 4; nt++)
                    mma_tf32(acc[mt][nt], af[mt], bf[nt]);
        }
        __syncthreads();
    }

    // epilogue
    #pragma unroll
    for (int mt = 0; mt < 4; mt++) {
        #pragma unroll
        for (int half = 0; half < 2; half++) {
            int row = bm * 128 + wm0 + mt * 16 + g + half * 8;
            #pragma unroll
            for (int nt = 0; nt < 4; nt++) {
                int col = bn * 128 + wn0 + nt * 8 + 2 * t;
                float vx = acc[mt][nt][2 * half + 0] + bias[col];
                float vy = acc[mt][nt][2 * half + 1] + bias[col + 1];
                if (mode == 1) {
                    vx *= 1.f / (1.f + __expf(-1.702f * vx));
                    vy *= 1.f / (1.f + __expf(-1.702f * vy));
                    uint32_t* Co = (uint32_t*)Cout + (size_t)row * N;
                    Co[PCOL(col)]     = f2tf32(vx);
                    Co[PCOL(col + 1)] = f2tf32(vy);
                } else {
                    if (mode == 2) {
                        float2 rs = *(const float2*)(resid + (size_t)row * N + col);
                        vx += rs.x; vy += rs.y;
                    }
                    float2 v = make_float2(vx, vy);
                    *(float2*)((float*)Cout + (size_t)row * N + col) = v;
                }
            }
        }
    }
}

// ---------------- LayerNorm -> tf32-permuted output ----------------
__global__ void ln_kernel(const float* __restrict__ x, const float* __restrict__ g,
                          const float* __restrict__ b, uint32_t* __restrict__ out) {
    int row = blockIdx.x;
    const float* xr = x + (size_t)row * DIM;
    uint32_t* orow = out + (size_t)row * DIM;
    int tid = threadIdx.x;

    float s = 0.f, ss = 0.f;
    for (int i = tid; i < DIM; i += 256) { float v = xr[i]; s += v; ss += v * v; }
    __shared__ float red0[8], red1[8];
    #pragma unroll
    for (int o = 16; o > 0; o >>= 1) {
        s  += __shfl_xor_sync(0xffffffffu, s, o);
        ss += __shfl_xor_sync(0xffffffffu, ss, o);
    }
    if ((tid & 31) == 0) { red0[tid >> 5] = s; red1[tid >> 5] = ss; }
    __syncthreads();
    float st = 0.f, sst = 0.f;
    #pragma unroll
    for (int i = 0; i < 8; i++) { st += red0[i]; sst += red1[i]; }
    float mean = st * (1.f / DIM);
    float var  = sst * (1.f / DIM) - mean * mean;
    float rstd = rsqrtf(var + 1e-5f);
    for (int i = tid; i < DIM; i += 256)
        orow[PCOL(i)] = f2tf32((xr[i] - mean) * rstd * g[i] + b[i]);
}

// ---------------- fused attention (flash-style, fp32 SIMT) -> tf32-perm out ------
#define ATT_SMEM_FLOATS (64*64 + 64*64 + 64*68 + 64*68 + 3*64)
#define ATT_SMEM_BYTES  (ATT_SMEM_FLOATS * 4)

__global__ void attn_kernel(const float* __restrict__ qkv, const float* __restrict__ prompt,
                            uint32_t* __restrict__ out) {
    extern __shared__ float smf[];
    float* Qt   = smf;
    float* Kt   = Qt + 64 * 64;
    float* Vs   = Kt + 64 * 64;
    float* St   = Vs + 64 * 68;
    float* mrow = St + 64 * 68;
    float* lrow = mrow + 64;
    float* arow = lrow + 64;

    int qt = blockIdx.x, h = blockIdx.y, b = blockIdx.z;
    int tid = threadIdx.x;
    int tx = tid & 15, ty = tid >> 4;

    {
        int q = tid & 63, ch = tid >> 6;
        int n = qt * 64 + q;
        const float* src = qkv + (size_t)(b * SEQ + n) * (3 * DIM) + (0 * NH + h) * HDIM + ch * 16;
        #pragma unroll
        for (int ii = 0; ii < 4; ii++) {
            float4 v = *(const float4*)(src + ii * 4);
            int d = ch * 16 + ii * 4;
            Qt[(d + 0) * 64 + q] = v.x * 0.125f;
            Qt[(d + 1) * 64 + q] = v.y * 0.125f;
            Qt[(d + 2) * 64 + q] = v.z * 0.125f;
            Qt[(d + 3) * 64 + q] = v.w * 0.125f;
        }
    }
    if (tid < 64) { mrow[tid] = -1e30f; lrow[tid] = 0.f; }

    float o[4][4] = {};

    for (int kt = 0; kt < 17; kt++) {
        __syncthreads();
        {
            int key = tid & 63, ch = tid >> 6;
            int kg = kt * 64 + key;
            bool valid = kg < KEYS;
            const float* src = nullptr;
            if (valid) {
                if (kg < PLEN)
                    src = prompt + ((((size_t)b * 2 + 0) * PLEN + kg) * NH + h) * HDIM + ch * 16;
                else
                    src = qkv + (size_t)(b * SEQ + (kg - PLEN)) * (3 * DIM) + (1 * NH + h) * HDIM + ch * 16;
            }
            #pragma unroll
            for (int ii = 0; ii < 4; ii++) {
                float4 v = valid ? *(const float4*)(src + ii * 4) : make_float4(0.f, 0.f, 0.f, 0.f);
                int d = ch * 16 + ii * 4;
                Kt[(d + 0) * 64 + key] = v.x;
                Kt[(d + 1) * 64 + key] = v.y;
                Kt[(d + 2) * 64 + key] = v.z;
                Kt[(d + 3) * 64 + key] = v.w;
            }
        }
        {
            int key = tid >> 2, part = tid & 3;
            int kg = kt * 64 + key;
            bool valid = kg < KEYS;
            const float* src = nullptr;
            if (valid) {
                if (kg < PLEN)
                    src = prompt + ((((size_t)b * 2 + 1) * PLEN + kg) * NH + h) * HDIM + part * 16;
                else
                    src = qkv + (size_t)(b * SEQ + (kg - PLEN)) * (3 * DIM) + (2 * NH + h) * HDIM + part * 16;
            }
            #pragma unroll
            for (int ii = 0; ii < 4; ii++) {
                float4 v = valid ? *(const float4*)(src + ii * 4) : make_float4(0.f, 0.f, 0.f, 0.f);
                *(float4*)&Vs[key * 68 + part * 16 + ii * 4] = v;
            }
        }
        __syncthreads();

        float sacc[4][4] = {};
        #pragma unroll 16
        for (int d = 0; d < 64; d++) {
            float4 a  = *(const float4*)&Qt[d * 64 + ty * 4];
            float4 bb = *(const float4*)&Kt[d * 64 + tx * 4];
            float av[4] = {a.x, a.y, a.z, a.w};
            float bv[4] = {bb.x, bb.y, bb.z, bb.w};
            #pragma unroll
            for (int i = 0; i < 4; i++)
                #pragma unroll
                for (int j = 0; j < 4; j++)
                    sacc[i][j] += av[i] * bv[j];
        }
        #pragma unroll
        for (int j = 0; j < 4; j++) {
            int kg = kt * 64 + tx * 4 + j;
            float4 w = (kg < KEYS)
                ? make_float4(sacc[0][j], sacc[1][j], sacc[2][j], sacc[3][j])
                : make_float4(-1e30f, -1e30f, -1e30f, -1e30f);
            *(float4*)&St[(tx * 4 + j) * 68 + ty * 4] = w;
        }
        __syncthreads();

        {
            int q = tid >> 2, part = tid & 3;
            float mt = -1e30f;
            #pragma unroll
            for (int i = 0; i < 16; i++) mt = fmaxf(mt, St[(part * 16 + i) * 68 + q]);
            mt = fmaxf(mt, __shfl_xor_sync(0xffffffffu, mt, 1));
            mt = fmaxf(mt, __shfl_xor_sync(0xffffffffu, mt, 2));
            float mold = mrow[q];
            float mnew = fmaxf(mold, mt);
            float lsum = 0.f;
            #pragma unroll
            for (int i = 0; i < 16; i++) {
                float p = __expf(St[(part * 16 + i) * 68 + q] - mnew);
                St[(part * 16 + i) * 68 + q] = p;
                lsum += p;
            }
            lsum += __shfl_xor_sync(0xffffffffu, lsum, 1);
            lsum += __shfl_xor_sync(0xffffffffu, lsum, 2);
            float alpha = __expf(mold - mnew);
            if (part == 0) {
                mrow[q] = mnew;
                lrow[q] = lrow[q] * alpha + lsum;
                arow[q] = alpha;
            }
        }
        __syncthreads();

        float al[4];
        #pragma unroll
        for (int i = 0; i < 4; i++) al[i] = arow[ty * 4 + i];
        #pragma unroll
        for (int i = 0; i < 4; i++)
            #pragma unroll
            for (int j = 0; j < 4; j++)
                o[i][j] *= al[i];
        #pragma unroll 16
        for (int kk = 0; kk < 64; kk++) {
            float4 p = *(const float4*)&St[kk * 68 + ty * 4];
            float4 v = *(const float4*)&Vs[kk * 68 + tx * 4];
            float pv[4] = {p.x, p.y, p.z, p.w};
            float vv[4] = {v.x, v.y, v.z, v.w};
            #pragma unroll
            for (int i = 0; i < 4; i++)
                #pragma unroll
                for (int j = 0; j < 4; j++)
                    o[i][j] += pv[i] * vv[j];
        }
    }

    #pragma unroll
    for (int i = 0; i < 4; i++) {
        float linv = 1.f / lrow[ty * 4 + i];
        int n = qt * 64 + ty * 4 + i;
        uint32_t* orow = out + (size_t)(b * SEQ + n) * DIM;
        #pragma unroll
        for (int j = 0; j < 4; j++) {
            int col = h * HDIM + tx * 4 + j;
            orow[PCOL(col)] = f2tf32(o[i][j] * linv);
        }
    }
}

// ---------------- launch ----------------
extern "C" void kernel_launch(void* const* d_in, const int* in_sizes, int n_in,
                              void* d_out, int out_size) {
    const float* x      = (const float*)d_in[0];
    const float* prompt = (const float*)d_in[1];
    const float* qkv_w  = (const float*)d_in[2];
    const float* qkv_b  = (const float*)d_in[3];
    const float* out_w  = (const float*)d_in[4];
    const float* out_b  = (const float*)d_in[5];
    const float* ln1_g  = (const float*)d_in[6];
    const float* ln1_b  = (const float*)d_in[7];
    const float* ln2_g  = (const float*)d_in[8];
    const float* ln2_b  = (const float*)d_in[9];
    const float* fc1_w  = (const float*)d_in[10];
    const float* fc1_b  = (const float*)d_in[11];
    const float* fc2_w  = (const float*)d_in[12];
    const float* fc2_b  = (const float*)d_in[13];
    float* out = (float*)d_out;

    uint32_t *h, *attn, *ff, *wq, *wo, *wf1, *wf2;
    float *qkv, *xr;
    cudaGetSymbolAddress((void**)&h,    g_h);
    cudaGetSymbolAddress((void**)&qkv,  g_qkv);
    cudaGetSymbolAddress((void**)&attn, g_attn);
    cudaGetSymbolAddress((void**)&xr,   g_xr);
    cudaGetSymbolAddress((void**)&ff,   g_ff);
    cudaGetSymbolAddress((void**)&wq,   g_wq);
    cudaGetSymbolAddress((void**)&wo,   g_wo);
    cudaGetSymbolAddress((void**)&wf1,  g_wf1);
    cudaGetSymbolAddress((void**)&wf2,  g_wf2);

    cudaFuncSetAttribute(attn_kernel, cudaFuncAttributeMaxDynamicSharedMemorySize, ATT_SMEM_BYTES);
    cudaFuncSetAttribute(mma_gemm, cudaFuncAttributeMaxDynamicSharedMemorySize, GSM_BYTES);

    // 0) weight conversion to tf32-perm
    cvt_w<<<(3 * DIM * DIM + 255) / 256, 256>>>(qkv_w, wq, 3 * DIM * DIM, DIM);
    cvt_w<<<(DIM * DIM + 255) / 256, 256>>>(out_w, wo, DIM * DIM, DIM);
    cvt_w<<<(FFD * DIM + 255) / 256, 256>>>(fc1_w, wf1, FFD * DIM, DIM);
    cvt_w<<<(DIM * FFD + 255) / 256, 256>>>(fc2_w, wf2, DIM * FFD, FFD);

    // 1) h = LN1(x)  (tf32-perm)
    ln_kernel<<<ROWS, 256>>>(x, ln1_g, ln1_b, h);
    // 2) qkv = h @ qkv_w^T + qkv_b  (fp32 out)
    mma_gemm<<<dim3(3 * DIM / 128, ROWS / 128), 256, GSM_BYTES>>>(h, wq, qkv_b, nullptr, qkv,
                                                                  ROWS, 3 * DIM, DIM, 0);
    // 3) attention (tf32-perm out)
    attn_kernel<<<dim3(SEQ / 64, NH, BSZ), 256, ATT_SMEM_BYTES>>>(qkv, prompt, attn);
    // 4) xr = x + attn @ out_w^T + out_b  (fp32 out)
    mma_gemm<<<dim3(DIM / 128, ROWS / 128), 256, GSM_BYTES>>>(attn, wo, out_b, x, xr,
                                                              ROWS, DIM, DIM, 2);
    // 5) h = LN2(xr)  (tf32-perm)
    ln_kernel<<<ROWS, 256>>>(xr, ln2_g, ln2_b, h);
    // 6) ff = quickgelu(h @ fc1_w^T + fc1_b)  (tf32-perm out)
    mma_gemm<<<dim3(FFD / 128, ROWS / 128), 256, GSM_BYTES>>>(h, wf1, fc1_b, nullptr, ff,
                                                              ROWS, FFD, DIM, 1);
    // 7) out = xr + ff @ fc2_w^T + fc2_b  (fp32 out)
    mma_gemm<<<dim3(DIM / 128, ROWS / 128), 256, GSM_BYTES>>>(ff, wf2, fc2_b, xr, out,
                                                              ROWS, DIM, FFD, 2);
}

// round 5
// speedup vs baseline: 1.7092x; 1.0474x over previous
#include <cuda_runtime.h>
#include <cstdint>

// ---------------- problem constants ----------------
#define BSZ   16
#define SEQ   1024
#define DIM   768
#define NH    12
#define HDIM  64
#define PLEN  16
#define KEYS  (PLEN + SEQ)       // 1040
#define FFD   (4 * DIM)          // 3072
#define ROWS  (BSZ * SEQ)        // 16384

// within-8 k permutation so mma pair (t, t+4) is adjacent
#define PCOL(k) (((k) & ~7) | ((((k) & 3) << 1) | (((k) >> 2) & 1)))

// ---------------- scratch (device globals: no alloc allowed) ----------------
__device__ uint32_t g_h   [(size_t)ROWS * DIM];     // LN out, tf32-perm
__device__ float    g_qkv [(size_t)ROWS * 3 * DIM]; // fp32
__device__ uint32_t g_attn[(size_t)ROWS * DIM];     // attn out, tf32-perm
__device__ float    g_xr  [(size_t)ROWS * DIM];     // residual 1, fp32
__device__ uint32_t g_ff  [(size_t)ROWS * FFD];     // gelu out, tf32-perm
__device__ uint32_t g_wq  [(size_t)3 * DIM * DIM];  // weights tf32-perm
__device__ uint32_t g_wo  [(size_t)DIM * DIM];
__device__ uint32_t g_wf1 [(size_t)FFD * DIM];
__device__ uint32_t g_wf2 [(size_t)DIM * FFD];

// ---------------- helpers ----------------
__device__ __forceinline__ uint32_t f2tf32(float f) {
    uint32_t r;
    asm("cvt.rna.tf32.f32 %0, %1;" : "=r"(r) : "f"(f));
    return r;
}
__device__ __forceinline__ uint32_t smem_u32(const void* p) {
    uint32_t a;
    asm("{ .reg .u64 t; cvta.to.shared.u64 t, %1; cvt.u32.u64 %0, t; }" : "=r"(a) : "l"(p));
    return a;
}
__device__ __forceinline__ void cp_async16(uint32_t dst, const void* src) {
    asm volatile("cp.async.cg.shared.global [%0], [%1], 16;" :: "r"(dst), "l"(src) : "memory");
}
#define CP_COMMIT() asm volatile("cp.async.commit_group;" ::: "memory")
#define CP_WAIT(n)  asm volatile("cp.async.wait_group %0;" :: "n"(n) : "memory")

__device__ __forceinline__ void mma_tf32(float* c, const uint32_t* a, const uint32_t* b) {
    asm volatile(
        "mma.sync.aligned.m16n8k8.row.col.f32.tf32.tf32.f32 "
        "{%0,%1,%2,%3}, {%4,%5,%6,%7}, {%8,%9}, {%0,%1,%2,%3};"
        : "+f"(c[0]), "+f"(c[1]), "+f"(c[2]), "+f"(c[3])
        : "r"(a[0]), "r"(a[1]), "r"(a[2]), "r"(a[3]), "r"(b[0]), "r"(b[1]));
}

// ---------------- weight convert: fp32 -> tf32-perm ----------------
__global__ void cvt_w(const float* __restrict__ in, uint32_t* __restrict__ out, int total, int K) {
    int idx = blockIdx.x * 256 + threadIdx.x;
    if (idx >= total) return;
    int row = idx / K, k = idx - row * K;
    out[(size_t)row * K + PCOL(k)] = f2tf32(in[idx]);
}

// ---------------- tf32 mma.sync GEMM, 3-stage cp.async pipeline ----------------
// C = A @ W^T + bias, modes: 0 = fp32 out, 1 = gelu + tf32-perm out, 2 = resid + fp32 out
// 128x128 CTA tile, 8 warps of 64x32, K-chunks of 32, triple buffer, pad GP=36.
#define GP        36
#define GBUF      (128 * GP)
#define GSM_A(s)  ((s) * GBUF)
#define GSM_B(s)  (3 * GBUF + (s) * GBUF)
#define GSM_BYTES (6 * GBUF * 4)

__global__ void __launch_bounds__(256, 2)
mma_gemm(const uint32_t* __restrict__ A, const uint32_t* __restrict__ W,
         const float* __restrict__ bias, const float* __restrict__ resid,
         void* __restrict__ Cout, int M, int N, int K, int mode) {
    extern __shared__ uint32_t smu[];
    int tid = threadIdx.x;
    int wid = tid >> 5, lane = tid & 31;
    int g = lane >> 2, t = lane & 3;
    int bm = blockIdx.y, bn = blockIdx.x;
    int wm0 = (wid & 1) * 64, wn0 = (wid >> 1) * 32;

    int r  = tid >> 1;
    int hf = (tid & 1) << 4;
    const uint32_t* Ap = A + (size_t)(bm * 128 + r) * K + hf;
    const uint32_t* Wp = W + (size_t)(bn * 128 + r) * K + hf;
    uint32_t smA_dst[3], smB_dst[3];
    {
        uint32_t base = smem_u32(smu);
        #pragma unroll
        for (int s = 0; s < 3; s++) {
            smA_dst[s] = base + (GSM_A(s) + r * GP + hf) * 4;
            smB_dst[s] = base + (GSM_B(s) + r * GP + hf) * 4;
        }
    }

    float acc[4][4][4] = {};
    int nc = K >> 5;

    // prologue: chunks 0,1
    #pragma unroll
    for (int i = 0; i < 4; i++) cp_async16(smA_dst[0] + i * 16, Ap + i * 4);
    #pragma unroll
    for (int i = 0; i < 4; i++) cp_async16(smB_dst[0] + i * 16, Wp + i * 4);
    CP_COMMIT();
    #pragma unroll
    for (int i = 0; i < 4; i++) cp_async16(smA_dst[1] + i * 16, Ap + 32 + i * 4);
    #pragma unroll
    for (int i = 0; i < 4; i++) cp_async16(smB_dst[1] + i * 16, Wp + 32 + i * 4);
    CP_COMMIT();

    for (int c = 0; c < nc; c++) {
        int s = c % 3;
        if (c + 2 < nc) {
            int s2 = (c + 2) % 3;
            const uint32_t* ap = Ap + (c + 2) * 32;
            const uint32_t* wp = Wp + (c + 2) * 32;
            #pragma unroll
            for (int i = 0; i < 4; i++) cp_async16(smA_dst[s2] + i * 16, ap + i * 4);
            #pragma unroll
            for (int i = 0; i < 4; i++) cp_async16(smB_dst[s2] + i * 16, wp + i * 4);
            CP_COMMIT();
            CP_WAIT(2);
        } else if (c + 1 < nc) {
            CP_WAIT(1);
        } else {
            CP_WAIT(0);
        }
        __syncthreads();

        const uint32_t* As_ = smu + GSM_A(s);
        const uint32_t* Bs_ = smu + GSM_B(s);
        #pragma unroll
        for (int k0 = 0; k0 < 32; k0 += 8) {
            uint32_t af[4][4], bf[4][2];
            #pragma unroll
            for (int mt = 0; mt < 4; mt++) {
                int r0 = wm0 + mt * 16 + g;
                uint2 lo = *(const uint2*)(As_ + r0 * GP + k0 + 2 * t);
                uint2 hi = *(const uint2*)(As_ + (r0 + 8) * GP + k0 + 2 * t);
                af[mt][0] = lo.x; af[mt][2] = lo.y;
                af[mt][1] = hi.x; af[mt][3] = hi.y;
            }
            #pragma unroll
            for (int nt = 0; nt < 4; nt++) {
                int n0 = wn0 + nt * 8 + g;
                uint2 bv = *(const uint2*)(Bs_ + n0 * GP + k0 + 2 * t);
                bf[nt][0] = bv.x; bf[nt][1] = bv.y;
            }
            #pragma unroll
            for (int mt = 0; mt < 4; mt++)
                #pragma unroll
                for (int nt = 0; nt < 4; nt++)
                    mma_tf32(acc[mt][nt], af[mt], bf[nt]);
        }
        __syncthreads();
    }

    // epilogue
    #pragma unroll
    for (int mt = 0; mt < 4; mt++) {
        #pragma unroll
        for (int half = 0; half < 2; half++) {
            int row = bm * 128 + wm0 + mt * 16 + g + half * 8;
            #pragma unroll
            for (int nt = 0; nt < 4; nt++) {
                int col = bn * 128 + wn0 + nt * 8 + 2 * t;
                float vx = acc[mt][nt][2 * half + 0] + bias[col];
                float vy = acc[mt][nt][2 * half + 1] + bias[col + 1];
                if (mode == 1) {
                    vx *= 1.f / (1.f + __expf(-1.702f * vx));
                    vy *= 1.f / (1.f + __expf(-1.702f * vy));
                    uint32_t* Co = (uint32_t*)Cout + (size_t)row * N;
                    Co[PCOL(col)]     = f2tf32(vx);
                    Co[PCOL(col + 1)] = f2tf32(vy);
                } else {
                    if (mode == 2) {
                        float2 rs = *(const float2*)(resid + (size_t)row * N + col);
                        vx += rs.x; vy += rs.y;
                    }
                    *(float2*)((float*)Cout + (size_t)row * N + col) = make_float2(vx, vy);
                }
            }
        }
    }
}

// ---------------- LayerNorm -> tf32-permuted output ----------------
__global__ void ln_kernel(const float* __restrict__ x, const float* __restrict__ g,
                          const float* __restrict__ b, uint32_t* __restrict__ out) {
    int row = blockIdx.x;
    const float* xr = x + (size_t)row * DIM;
    uint32_t* orow = out + (size_t)row * DIM;
    int tid = threadIdx.x;

    float s = 0.f, ss = 0.f;
    for (int i = tid; i < DIM; i += 256) { float v = xr[i]; s += v; ss += v * v; }
    __shared__ float red0[8], red1[8];
    #pragma unroll
    for (int o = 16; o > 0; o >>= 1) {
        s  += __shfl_xor_sync(0xffffffffu, s, o);
        ss += __shfl_xor_sync(0xffffffffu, ss, o);
    }
    if ((tid & 31) == 0) { red0[tid >> 5] = s; red1[tid >> 5] = ss; }
    __syncthreads();
    float st = 0.f, sst = 0.f;
    #pragma unroll
    for (int i = 0; i < 8; i++) { st += red0[i]; sst += red1[i]; }
    float mean = st * (1.f / DIM);
    float var  = sst * (1.f / DIM) - mean * mean;
    float rstd = rsqrtf(var + 1e-5f);
    for (int i = tid; i < DIM; i += 256)
        orow[PCOL(i)] = f2tf32((xr[i] - mean) * rstd * g[i] + b[i]);
}

// ---------------- fused attention: tf32 mma.sync flash attention ----------------
// block = 256 threads (8 warps). q-tile 64, key-tiles of 64 (17 iters).
// smem (u32): Qs[64][68] tf32, Ks[64][68] tf32, Vt[64][68] tf32, Sb[64][68] f32/tf32,
//             mrow/lrow/arow[64] f32.
#define AQS 0
#define AKS 4352
#define AVT 8704
#define ASB 13056
#define AMR 17408
#define ALR 17472
#define AAR 17536
#define ATT_SMEM_BYTES (17600 * 4)

__global__ void __launch_bounds__(256, 3)
attn_kernel(const float* __restrict__ qkv, const float* __restrict__ prompt,
            uint32_t* __restrict__ out) {
    extern __shared__ uint32_t su[];
    uint32_t* Qs  = su + AQS;
    uint32_t* Ks  = su + AKS;
    uint32_t* Vt  = su + AVT;
    float*    Sb  = (float*)(su + ASB);
    uint32_t* Sbu = su + ASB;
    float* mrow = (float*)(su + AMR);
    float* lrow = (float*)(su + ALR);
    float* arow = (float*)(su + AAR);

    int qt = blockIdx.x, h = blockIdx.y, b = blockIdx.z;
    int tid = threadIdx.x;
    int wid = tid >> 5, lane = tid & 31;
    int g = lane >> 2, t = lane & 3;
    int q0 = (wid & 3) * 16;       // warp's 16-q rows
    int n0 = (wid >> 2) * 32;      // warp's 32 cols (keys in QK, d in PV)

    // --- Q tile load: tf32-perm, scaled 0.125 ---
    {
        int q = tid & 63, ch = tid >> 6;
        int n = qt * 64 + q;
        const float* src = qkv + (size_t)(b * SEQ + n) * (3 * DIM) + h * HDIM + ch * 16;
        #pragma unroll
        for (int ii = 0; ii < 4; ii++) {
            float4 v = *(const float4*)(src + ii * 4);
            int d = ch * 16 + ii * 4;
            Qs[q * 68 + PCOL(d + 0)] = f2tf32(v.x * 0.125f);
            Qs[q * 68 + PCOL(d + 1)] = f2tf32(v.y * 0.125f);
            Qs[q * 68 + PCOL(d + 2)] = f2tf32(v.z * 0.125f);
            Qs[q * 68 + PCOL(d + 3)] = f2tf32(v.w * 0.125f);
        }
    }
    if (tid < 64) { mrow[tid] = -1e30f; lrow[tid] = 0.f; }

    float acc_o[4][4] = {};

    for (int kt = 0; kt < 17; kt++) {
        __syncthreads();   // prev PV done -> Ks/Vt/Sb reusable
        // --- K tile -> Ks[key][PCOL(d)] tf32 ---
        {
            int key = tid & 63, ch = tid >> 6;
            int kg = kt * 64 + key;
            bool valid = kg < KEYS;
            const float* src = nullptr;
            if (valid) {
                if (kg < PLEN)
                    src = prompt + ((((size_t)b * 2 + 0) * PLEN + kg) * NH + h) * HDIM + ch * 16;
                else
                    src = qkv + (size_t)(b * SEQ + (kg - PLEN)) * (3 * DIM) + (1 * NH + h) * HDIM + ch * 16;
            }
            #pragma unroll
            for (int ii = 0; ii < 4; ii++) {
                float4 v = valid ? *(const float4*)(src + ii * 4) : make_float4(0.f, 0.f, 0.f, 0.f);
                int d = ch * 16 + ii * 4;
                Ks[key * 68 + PCOL(d + 0)] = f2tf32(v.x);
                Ks[key * 68 + PCOL(d + 1)] = f2tf32(v.y);
                Ks[key * 68 + PCOL(d + 2)] = f2tf32(v.z);
                Ks[key * 68 + PCOL(d + 3)] = f2tf32(v.w);
            }
        }
        // --- V tile -> Vt[d][PCOL(key)] tf32 (transposed; zero when invalid) ---
        {
            int key = tid >> 2, part = tid & 3;
            int kg = kt * 64 + key;
            bool valid = kg < KEYS;
            int pk = PCOL(key);
            const float* src = nullptr;
            if (valid) {
                if (kg < PLEN)
                    src = prompt + ((((size_t)b * 2 + 1) * PLEN + kg) * NH + h) * HDIM + part * 16;
                else
                    src = qkv + (size_t)(b * SEQ + (kg - PLEN)) * (3 * DIM) + (2 * NH + h) * HDIM + part * 16;
            }
            #pragma unroll
            for (int ii = 0; ii < 4; ii++) {
                float4 v = valid ? *(const float4*)(src + ii * 4) : make_float4(0.f, 0.f, 0.f, 0.f);
                int d = part * 16 + ii * 4;
                Vt[(d + 0) * 68 + pk] = f2tf32(v.x);
                Vt[(d + 1) * 68 + pk] = f2tf32(v.y);
                Vt[(d + 2) * 68 + pk] = f2tf32(v.z);
                Vt[(d + 3) * 68 + pk] = f2tf32(v.w);
            }
        }
        __syncthreads();

        // --- S = Q @ K^T  (warp tile 16q x 32key), d-loop 8 steps ---
        float s4[4][4] = {};
        #pragma unroll
        for (int k0 = 0; k0 < 64; k0 += 8) {
            uint32_t af[4];
            uint2 lo = *(const uint2*)(Qs + (q0 + g) * 68 + k0 + 2 * t);
            uint2 hi = *(const uint2*)(Qs + (q0 + g + 8) * 68 + k0 + 2 * t);
            af[0] = lo.x; af[2] = lo.y; af[1] = hi.x; af[3] = hi.y;
            #pragma unroll
            for (int nt = 0; nt < 4; nt++) {
                uint2 bv = *(const uint2*)(Ks + (n0 + nt * 8 + g) * 68 + k0 + 2 * t);
                uint32_t bf[2] = { bv.x, bv.y };
                mma_tf32(s4[nt], af, bf);
            }
        }
        #pragma unroll
        for (int nt = 0; nt < 4; nt++) {
            *(float2*)(Sb + (q0 + g) * 68 + n0 + nt * 8 + 2 * t)     = make_float2(s4[nt][0], s4[nt][1]);
            *(float2*)(Sb + (q0 + g + 8) * 68 + n0 + nt * 8 + 2 * t) = make_float2(s4[nt][2], s4[nt][3]);
        }
        __syncthreads();

        // --- online softmax (4 threads per q row, 16 keys each); P -> tf32-perm in place ---
        {
            int q = tid >> 2, part = tid & 3;
            int base = part * 16;
            float vals[16];
            #pragma unroll
            for (int i = 0; i < 16; i++) {
                int kg = kt * 64 + base + i;
                vals[i] = (kg < KEYS) ? Sb[q * 68 + base + i] : -1e30f;
            }
            float mt = -1e30f;
            #pragma unroll
            for (int i = 0; i < 16; i++) mt = fmaxf(mt, vals[i]);
            mt = fmaxf(mt, __shfl_xor_sync(0xffffffffu, mt, 1));
            mt = fmaxf(mt, __shfl_xor_sync(0xffffffffu, mt, 2));
            float mold = mrow[q];
            float mnew = fmaxf(mold, mt);
            float ls = 0.f;
            #pragma unroll
            for (int i = 0; i < 16; i++) {
                float p = __expf(vals[i] - mnew);
                ls += p;
                Sbu[q * 68 + PCOL(base + i)] = f2tf32(p);
            }
            ls += __shfl_xor_sync(0xffffffffu, ls, 1);
            ls += __shfl_xor_sync(0xffffffffu, ls, 2);
            float alpha = __expf(mold - mnew);
            if (part == 0) {
                mrow[q] = mnew;
                lrow[q] = lrow[q] * alpha + ls;
                arow[q] = alpha;
            }
        }
        __syncthreads();

        // --- O = O*alpha + P @ V  (warp tile 16q x 32d), key-loop 8 steps ---
        float al0 = arow[q0 + g], al1 = arow[q0 + g + 8];
        #pragma unroll
        for (int nt = 0; nt < 4; nt++) {
            acc_o[nt][0] *= al0; acc_o[nt][1] *= al0;
            acc_o[nt][2] *= al1; acc_o[nt][3] *= al1;
        }
        #pragma unroll
        for (int k0 = 0; k0 < 64; k0 += 8) {
            uint32_t af[4];
            uint2 lo = *(const uint2*)(Sbu + (q0 + g) * 68 + k0 + 2 * t);
            uint2 hi = *(const uint2*)(Sbu + (q0 + g + 8) * 68 + k0 + 2 * t);
            af[0] = lo.x; af[2] = lo.y; af[1] = hi.x; af[3] = hi.y;
            #pragma unroll
            for (int nt = 0; nt < 4; nt++) {
                uint2 bv = *(const uint2*)(Vt + (n0 + nt * 8 + g) * 68 + k0 + 2 * t);
                uint32_t bf[2] = { bv.x, bv.y };
                mma_tf32(acc_o[nt], af, bf);
            }
        }
    }

    // --- finalize: /l, write tf32-perm [B,N,H*HD] ---
    float li0 = 1.f / lrow[q0 + g];
    float li1 = 1.f / lrow[q0 + g + 8];
    int nrow0 = qt * 64 + q0 + g;
    uint32_t* o0 = out + (size_t)(b * SEQ + nrow0) * DIM;
    uint32_t* o1 = out + (size_t)(b * SEQ + nrow0 + 8) * DIM;
    #pragma unroll
    for (int nt = 0; nt < 4; nt++) {
        int col = h * HDIM + n0 + nt * 8 + 2 * t;
        o0[PCOL(col)]     = f2tf32(acc_o[nt][0] * li0);
        o0[PCOL(col + 1)] = f2tf32(acc_o[nt][1] * li0);
        o1[PCOL(col)]     = f2tf32(acc_o[nt][2] * li1);
        o1[PCOL(col + 1)] = f2tf32(acc_o[nt][3] * li1);
    }
}

// ---------------- launch ----------------
extern "C" void kernel_launch(void* const* d_in, const int* in_sizes, int n_in,
                              void* d_out, int out_size) {
    const float* x      = (const float*)d_in[0];
    const float* prompt = (const float*)d_in[1];
    const float* qkv_w  = (const float*)d_in[2];
    const float* qkv_b  = (const float*)d_in[3];
    const float* out_w  = (const float*)d_in[4];
    const float* out_b  = (const float*)d_in[5];
    const float* ln1_g  = (const float*)d_in[6];
    const float* ln1_b  = (const float*)d_in[7];
    const float* ln2_g  = (const float*)d_in[8];
    const float* ln2_b  = (const float*)d_in[9];
    const float* fc1_w  = (const float*)d_in[10];
    const float* fc1_b  = (const float*)d_in[11];
    const float* fc2_w  = (const float*)d_in[12];
    const float* fc2_b  = (const float*)d_in[13];
    float* out = (float*)d_out;

    uint32_t *h, *attn, *ff, *wq, *wo, *wf1, *wf2;
    float *qkv, *xr;
    cudaGetSymbolAddress((void**)&h,    g_h);
    cudaGetSymbolAddress((void**)&qkv,  g_qkv);
    cudaGetSymbolAddress((void**)&attn, g_attn);
    cudaGetSymbolAddress((void**)&xr,   g_xr);
    cudaGetSymbolAddress((void**)&ff,   g_ff);
    cudaGetSymbolAddress((void**)&wq,   g_wq);
    cudaGetSymbolAddress((void**)&wo,   g_wo);
    cudaGetSymbolAddress((void**)&wf1,  g_wf1);
    cudaGetSymbolAddress((void**)&wf2,  g_wf2);

    cudaFuncSetAttribute(attn_kernel, cudaFuncAttributeMaxDynamicSharedMemorySize, ATT_SMEM_BYTES);
    cudaFuncSetAttribute(mma_gemm, cudaFuncAttributeMaxDynamicSharedMemorySize, GSM_BYTES);

    // 0) weight conversion to tf32-perm
    cvt_w<<<(3 * DIM * DIM + 255) / 256, 256>>>(qkv_w, wq, 3 * DIM * DIM, DIM);
    cvt_w<<<(DIM * DIM + 255) / 256, 256>>>(out_w, wo, DIM * DIM, DIM);
    cvt_w<<<(FFD * DIM + 255) / 256, 256>>>(fc1_w, wf1, FFD * DIM, DIM);
    cvt_w<<<(DIM * FFD + 255) / 256, 256>>>(fc2_w, wf2, DIM * FFD, FFD);

    // 1) h = LN1(x)  (tf32-perm)
    ln_kernel<<<ROWS, 256>>>(x, ln1_g, ln1_b, h);
    // 2) qkv = h @ qkv_w^T + qkv_b  (fp32 out)
    mma_gemm<<<dim3(3 * DIM / 128, ROWS / 128), 256, GSM_BYTES>>>(h, wq, qkv_b, nullptr, qkv,
                                                                  ROWS, 3 * DIM, DIM, 0);
    // 3) attention (tensor-core flash, tf32-perm out)
    attn_kernel<<<dim3(SEQ / 64, NH, BSZ), 256, ATT_SMEM_BYTES>>>(qkv, prompt, attn);
    // 4) xr = x + attn @ out_w^T + out_b  (fp32 out)
    mma_gemm<<<dim3(DIM / 128, ROWS / 128), 256, GSM_BYTES>>>(attn, wo, out_b, x, xr,
                                                              ROWS, DIM, DIM, 2);
    // 5) h = LN2(xr)  (tf32-perm)
    ln_kernel<<<ROWS, 256>>>(xr, ln2_g, ln2_b, h);
    // 6) ff = quickgelu(h @ fc1_w^T + fc1_b)  (tf32-perm out)
    mma_gemm<<<dim3(FFD / 128, ROWS / 128), 256, GSM_BYTES>>>(h, wf1, fc1_b, nullptr, ff,
                                                              ROWS, FFD, DIM, 1);
    // 7) out = xr + ff @ fc2_w^T + fc2_b  (fp32 out)
    mma_gemm<<<dim3(DIM / 128, ROWS / 128), 256, GSM_BYTES>>>(ff, wf2, fc2_b, xr, out,
                                                              ROWS, DIM, FFD, 2);
}

// round 6
// speedup vs baseline: 2.9837x; 1.7457x over previous
#include <cuda_runtime.h>
#include <cuda_fp16.h>
#include <cstdint>

// ---------------- problem constants ----------------
#define BSZ   16
#define SEQ   1024
#define DIM   768
#define NH    12
#define HDIM  64
#define PLEN  16
#define KEYS  (PLEN + SEQ)       // 1040
#define FFD   (4 * DIM)          // 3072
#define ROWS  (BSZ * SEQ)        // 16384

// within-16 half permutation: k-pair p -> position ((p&3)<<1)|(p>>2), so pairs (t, t+4)
// are adjacent (one LDS.64 per fragment row for mma.m16n8k16).
#define PH(k) (((k) & ~15) | ((((((k) >> 1) & 3) << 1) | (((k) >> 3) & 1)) << 1) | ((k) & 1))

// ---------------- scratch (device globals: no alloc allowed) ----------------
__device__ __half g_h   [(size_t)ROWS * DIM];      // LN out, fp16-perm
__device__ __half g_qkv [(size_t)ROWS * 3 * DIM];  // qkv, fp16-perm
__device__ __half g_attn[(size_t)ROWS * DIM];      // attn out, fp16-perm
__device__ float  g_xr  [(size_t)ROWS * DIM];      // residual 1, fp32
__device__ __half g_ff  [(size_t)ROWS * FFD];      // gelu out, fp16-perm
__device__ __half g_wq  [(size_t)3 * DIM * DIM];   // weights fp16-perm
__device__ __half g_wo  [(size_t)DIM * DIM];
__device__ __half g_wf1 [(size_t)FFD * DIM];
__device__ __half g_wf2 [(size_t)DIM * FFD];

// ---------------- helpers ----------------
__device__ __forceinline__ uint32_t smem_u32(const void* p) {
    uint32_t a;
    asm("{ .reg .u64 t; cvta.to.shared.u64 t, %1; cvt.u32.u64 %0, t; }" : "=r"(a) : "l"(p));
    return a;
}
__device__ __forceinline__ void cp_async16(uint32_t dst, const void* src) {
    asm volatile("cp.async.cg.shared.global [%0], [%1], 16;" :: "r"(dst), "l"(src) : "memory");
}
#define CP_COMMIT() asm volatile("cp.async.commit_group;" ::: "memory")
#define CP_WAIT(n)  asm volatile("cp.async.wait_group %0;" :: "n"(n) : "memory")

__device__ __forceinline__ void mma_f16(float* c, const uint32_t* a, const uint32_t* b) {
    asm volatile(
        "mma.sync.aligned.m16n8k16.row.col.f32.f16.f16.f32 "
        "{%0,%1,%2,%3}, {%4,%5,%6,%7}, {%8,%9}, {%0,%1,%2,%3};"
        : "+f"(c[0]), "+f"(c[1]), "+f"(c[2]), "+f"(c[3])
        : "r"(a[0]), "r"(a[1]), "r"(a[2]), "r"(a[3]), "r"(b[0]), "r"(b[1]));
}

// ---------------- weight convert: fp32 -> fp16-perm ----------------
__global__ void cvt_w(const float* __restrict__ in, __half* __restrict__ out, int total, int K) {
    int idx = blockIdx.x * 256 + threadIdx.x;
    if (idx >= total) return;
    int row = idx / K, k = idx - row * K;
    out[(size_t)row * K + PH(k)] = __float2half(in[idx]);
}

// ---------------- fp16 mma.sync GEMM, 3-stage cp.async pipeline ----------------
// C = A @ W^T + bias. modes: 0 = fp16-perm out, 1 = gelu + fp16-perm out, 2 = resid + fp32 out
// 128x128 CTA tile, 8 warps of 64x32, K-chunks of 64 halves (128B/row), triple buffer.
// smem row stride 72 halves (144B = 36 u32). Buffer = 128*144 = 18432 B.
#define GBUFB     18432
#define ABUF(s)   ((s) * GBUFB)
#define BBUF(s)   (3 * GBUFB + (s) * GBUFB)
#define GSM_BYTES (6 * GBUFB)

__global__ void __launch_bounds__(256, 2)
mma_gemm(const __half* __restrict__ A, const __half* __restrict__ W,
         const float* __restrict__ bias, const float* __restrict__ resid,
         void* __restrict__ Cout, int M, int N, int K, int mode) {
    extern __shared__ char smc[];
    int tid = threadIdx.x;
    int wid = tid >> 5, lane = tid & 31;
    int g = lane >> 2, t = lane & 3;
    int bm = blockIdx.y, bn = blockIdx.x;
    int wm0 = (wid & 1) * 64, wn0 = (wid >> 1) * 32;

    int r  = tid >> 1;              // 0..127
    int hh = (tid & 1) << 5;        // half offset 0 or 32
    const __half* Ap = A + (size_t)(bm * 128 + r) * K + hh;
    const __half* Wp = W + (size_t)(bn * 128 + r) * K + hh;
    uint32_t smA_dst[3], smB_dst[3];
    {
        uint32_t base = smem_u32(smc);
        #pragma unroll
        for (int s = 0; s < 3; s++) {
            smA_dst[s] = base + ABUF(s) + r * 144 + hh * 2;
            smB_dst[s] = base + BBUF(s) + r * 144 + hh * 2;
        }
    }

    float acc[4][4][4] = {};
    int nc = K >> 6;                // chunks of 64 halves

    // prologue: chunks 0,1
    #pragma unroll
    for (int i = 0; i < 4; i++) cp_async16(smA_dst[0] + i * 16, Ap + i * 8);
    #pragma unroll
    for (int i = 0; i < 4; i++) cp_async16(smB_dst[0] + i * 16, Wp + i * 8);
    CP_COMMIT();
    #pragma unroll
    for (int i = 0; i < 4; i++) cp_async16(smA_dst[1] + i * 16, Ap + 64 + i * 8);
    #pragma unroll
    for (int i = 0; i < 4; i++) cp_async16(smB_dst[1] + i * 16, Wp + 64 + i * 8);
    CP_COMMIT();

    for (int c = 0; c < nc; c++) {
        int s = c % 3;
        if (c + 2 < nc) {
            int s2 = (c + 2) % 3;
            const __half* ap = Ap + (c + 2) * 64;
            const __half* wp = Wp + (c + 2) * 64;
            #pragma unroll
            for (int i = 0; i < 4; i++) cp_async16(smA_dst[s2] + i * 16, ap + i * 8);
            #pragma unroll
            for (int i = 0; i < 4; i++) cp_async16(smB_dst[s2] + i * 16, wp + i * 8);
            CP_COMMIT();
            CP_WAIT(2);
        } else if (c + 1 < nc) {
            CP_WAIT(1);
        } else {
            CP_WAIT(0);
        }
        __syncthreads();

        const char* As_ = smc + ABUF(s);
        const char* Bs_ = smc + BBUF(s);
        #pragma unroll
        for (int k0 = 0; k0 < 64; k0 += 16) {         // 4 k-steps of k16
            uint32_t af[4][4], bf[4][2];
            #pragma unroll
            for (int mt = 0; mt < 4; mt++) {
                int r0 = wm0 + mt * 16 + g;
                uint2 lo = *(const uint2*)(As_ + r0 * 144 + (k0 + 4 * t) * 2);
                uint2 hi = *(const uint2*)(As_ + (r0 + 8) * 144 + (k0 + 4 * t) * 2);
                af[mt][0] = lo.x; af[mt][2] = lo.y;
                af[mt][1] = hi.x; af[mt][3] = hi.y;
            }
            #pragma unroll
            for (int nt = 0; nt < 4; nt++) {
                int n0 = wn0 + nt * 8 + g;
                uint2 bv = *(const uint2*)(Bs_ + n0 * 144 + (k0 + 4 * t) * 2);
                bf[nt][0] = bv.x; bf[nt][1] = bv.y;
            }
            #pragma unroll
            for (int mt = 0; mt < 4; mt++)
                #pragma unroll
                for (int nt = 0; nt < 4; nt++)
                    mma_f16(acc[mt][nt], af[mt], bf[nt]);
        }
        __syncthreads();
    }

    // epilogue
    #pragma unroll
    for (int mt = 0; mt < 4; mt++) {
        #pragma unroll
        for (int half_ = 0; half_ < 2; half_++) {
            int row = bm * 128 + wm0 + mt * 16 + g + half_ * 8;
            #pragma unroll
            for (int nt = 0; nt < 4; nt++) {
                int col = bn * 128 + wn0 + nt * 8 + 2 * t;
                float vx = acc[mt][nt][2 * half_ + 0] + bias[col];
                float vy = acc[mt][nt][2 * half_ + 1] + bias[col + 1];
                if (mode == 2) {
                    float2 rs = *(const float2*)(resid + (size_t)row * N + col);
                    vx += rs.x; vy += rs.y;
                    *(float2*)((float*)Cout + (size_t)row * N + col) = make_float2(vx, vy);
                } else {
                    if (mode == 1) {
                        vx *= 1.f / (1.f + __expf(-1.702f * vx));
                        vy *= 1.f / (1.f + __expf(-1.702f * vy));
                    }
                    __half* Co = (__half*)Cout + (size_t)row * N;
                    *(__half2*)(Co + PH(col)) = __floats2half2_rn(vx, vy);
                }
            }
        }
    }
}

// ---------------- LayerNorm -> fp16-perm output ----------------
__global__ void ln_kernel(const float* __restrict__ x, const float* __restrict__ g,
                          const float* __restrict__ b, __half* __restrict__ out) {
    int row = blockIdx.x;
    const float* xr = x + (size_t)row * DIM;
    __half* orow = out + (size_t)row * DIM;
    int tid = threadIdx.x;

    float s = 0.f, ss = 0.f;
    for (int i = tid; i < DIM; i += 256) { float v = xr[i]; s += v; ss += v * v; }
    __shared__ float red0[8], red1[8];
    #pragma unroll
    for (int o = 16; o > 0; o >>= 1) {
        s  += __shfl_xor_sync(0xffffffffu, s, o);
        ss += __shfl_xor_sync(0xffffffffu, ss, o);
    }
    if ((tid & 31) == 0) { red0[tid >> 5] = s; red1[tid >> 5] = ss; }
    __syncthreads();
    float st = 0.f, sst = 0.f;
    #pragma unroll
    for (int i = 0; i < 8; i++) { st += red0[i]; sst += red1[i]; }
    float mean = st * (1.f / DIM);
    float var  = sst * (1.f / DIM) - mean * mean;
    float rstd = rsqrtf(var + 1e-5f);
    for (int i = tid; i < DIM; i += 256)
        orow[PH(i)] = __float2half((xr[i] - mean) * rstd * g[i] + b[i]);
}

// ---------------- fused attention: fp16 mma.sync flash attention ----------------
// 256 threads (8 warps), q-tile 64, key-tiles of 64 (17 iters).
// smem (u32 offsets): Qs 64x72h, Ks 64x72h, Vt 64x72h, Sb 64x68 f32, Ps 64x72h, m/l/a 64 f32
#define AQS 0
#define AKS 2304
#define AVT 4608
#define ASB 6912
#define APS 11264
#define AMR 13568
#define ALR 13632
#define AAR 13696
#define ATT_SMEM_BYTES (13760 * 4)

__global__ void __launch_bounds__(256, 3)
attn_kernel(const __half* __restrict__ qkv, const float* __restrict__ prompt,
            __half* __restrict__ out) {
    extern __shared__ uint32_t su[];
    __half* Qs = (__half*)(su + AQS);
    __half* Ks = (__half*)(su + AKS);
    __half* Vt = (__half*)(su + AVT);
    float*  Sb = (float*)(su + ASB);
    __half* Ps = (__half*)(su + APS);
    float* mrow = (float*)(su + AMR);
    float* lrow = (float*)(su + ALR);
    float* arow = (float*)(su + AAR);

    int qt = blockIdx.x, h = blockIdx.y, b = blockIdx.z;
    int tid = threadIdx.x;
    int wid = tid >> 5, lane = tid & 31;
    int g = lane >> 2, t = lane & 3;
    int q0 = (wid & 3) * 16;
    int n0 = (wid >> 2) * 32;

    // --- Q tile: verbatim copy (already fp16-perm in g_qkv) ---
    {
        int q = tid & 63, ch = tid >> 6;
        int n = qt * 64 + q;
        const __half* src = qkv + (size_t)(b * SEQ + n) * (3 * DIM) + h * HDIM + ch * 16;
        *(uint4*)(Qs + q * 72 + ch * 16)     = *(const uint4*)(src);
        *(uint4*)(Qs + q * 72 + ch * 16 + 8) = *(const uint4*)(src + 8);
    }
    if (tid < 64) { mrow[tid] = -1e30f; lrow[tid] = 0.f; }

    float acc_o[4][4] = {};

    for (int kt = 0; kt < 17; kt++) {
        __syncthreads();
        // --- K tile -> Ks[key][PH(d)] ---
        {
            int key = tid & 63, ch = tid >> 6;
            int kg = kt * 64 + key;
            if (kg >= KEYS) {
                uint4 z = make_uint4(0, 0, 0, 0);
                *(uint4*)(Ks + key * 72 + ch * 16)     = z;
                *(uint4*)(Ks + key * 72 + ch * 16 + 8) = z;
            } else if (kg >= PLEN) {
                const __half* src = qkv + (size_t)(b * SEQ + (kg - PLEN)) * (3 * DIM)
                                    + DIM + h * HDIM + ch * 16;
                *(uint4*)(Ks + key * 72 + ch * 16)     = *(const uint4*)(src);
                *(uint4*)(Ks + key * 72 + ch * 16 + 8) = *(const uint4*)(src + 8);
            } else {
                const float* src = prompt + ((((size_t)b * 2 + 0) * PLEN + kg) * NH + h) * HDIM + ch * 16;
                #pragma unroll
                for (int ii = 0; ii < 4; ii++) {
                    float4 v = *(const float4*)(src + ii * 4);
                    int d = ch * 16 + ii * 4;
                    Ks[key * 72 + PH(d + 0)] = __float2half(v.x);
                    Ks[key * 72 + PH(d + 1)] = __float2half(v.y);
                    Ks[key * 72 + PH(d + 2)] = __float2half(v.z);
                    Ks[key * 72 + PH(d + 3)] = __float2half(v.w);
                }
            }
        }
        // --- V tile -> Vt[d][PH(key)] (transposed) ---
        {
            int key = tid >> 2, part = tid & 3;
            int kg = kt * 64 + key;
            int pk = PH(key);
            if (kg >= KEYS) {
                #pragma unroll
                for (int i = 0; i < 16; i++)
                    Vt[(part * 16 + i) * 72 + pk] = __float2half(0.f);
            } else if (kg >= PLEN) {
                const uint32_t* sp = (const uint32_t*)(qkv + (size_t)(b * SEQ + (kg - PLEN)) * (3 * DIM)
                                                       + 2 * DIM + h * HDIM + part * 16);
                #pragma unroll
                for (int jj = 0; jj < 8; jj++) {
                    uint32_t pr = sp[jj];
                    int p = (jj >> 1) | ((jj & 1) << 2);   // inverse pair permutation
                    int d0 = part * 16 + 2 * p;
                    __half2 h2 = *(__half2*)&pr;
                    Vt[d0 * 72 + pk]       = __low2half(h2);
                    Vt[(d0 + 1) * 72 + pk] = __high2half(h2);
                }
            } else {
                const float* src = prompt + ((((size_t)b * 2 + 1) * PLEN + kg) * NH + h) * HDIM + part * 16;
                #pragma unroll
                for (int ii = 0; ii < 4; ii++) {
                    float4 v = *(const float4*)(src + ii * 4);
                    int d = part * 16 + ii * 4;
                    Vt[(d + 0) * 72 + pk] = __float2half(v.x);
                    Vt[(d + 1) * 72 + pk] = __float2half(v.y);
                    Vt[(d + 2) * 72 + pk] = __float2half(v.z);
                    Vt[(d + 3) * 72 + pk] = __float2half(v.w);
                }
            }
        }
        __syncthreads();

        // --- S = Q @ K^T (warp 16q x 32key), 4 k-steps of 16 ---
        float s4[4][4] = {};
        #pragma unroll
        for (int k0 = 0; k0 < 64; k0 += 16) {
            uint32_t af[4];
            uint2 lo = *(const uint2*)(Qs + (q0 + g) * 72 + k0 + 4 * t);
            uint2 hi = *(const uint2*)(Qs + (q0 + g + 8) * 72 + k0 + 4 * t);
            af[0] = lo.x; af[2] = lo.y; af[1] = hi.x; af[3] = hi.y;
            #pragma unroll
            for (int nt = 0; nt < 4; nt++) {
                uint2 bv = *(const uint2*)(Ks + (n0 + nt * 8 + g) * 72 + k0 + 4 * t);
                uint32_t bf[2] = { bv.x, bv.y };
                mma_f16(s4[nt], af, bf);
            }
        }
        #pragma unroll
        for (int nt = 0; nt < 4; nt++) {
            *(float2*)(Sb + (q0 + g) * 68 + n0 + nt * 8 + 2 * t)     = make_float2(s4[nt][0], s4[nt][1]);
            *(float2*)(Sb + (q0 + g + 8) * 68 + n0 + nt * 8 + 2 * t) = make_float2(s4[nt][2], s4[nt][3]);
        }
        __syncthreads();

        // --- online softmax (scale 0.125 applied here); P -> fp16-perm ---
        {
            int q = tid >> 2, part = tid & 3;
            int base = part * 16;
            float vals[16];
            #pragma unroll
            for (int i = 0; i < 16; i++) {
                int kg = kt * 64 + base + i;
                vals[i] = (kg < KEYS) ? Sb[q * 68 + base + i] * 0.125f : -1e30f;
            }
            float mt = -1e30f;
            #pragma unroll
            for (int i = 0; i < 16; i++) mt = fmaxf(mt, vals[i]);
            mt = fmaxf(mt, __shfl_xor_sync(0xffffffffu, mt, 1));
            mt = fmaxf(mt, __shfl_xor_sync(0xffffffffu, mt, 2));
            float mold = mrow[q];
            float mnew = fmaxf(mold, mt);
            float ls = 0.f;
            #pragma unroll
            for (int i = 0; i < 16; i++) {
                float p = __expf(vals[i] - mnew);
                ls += p;
                Ps[q * 72 + PH(base + i)] = __float2half(p);
            }
            ls += __shfl_xor_sync(0xffffffffu, ls, 1);
            ls += __shfl_xor_sync(0xffffffffu, ls, 2);
            float alpha = __expf(mold - mnew);
            if (part == 0) {
                mrow[q] = mnew;
                lrow[q] = lrow[q] * alpha + ls;
                arow[q] = alpha;
            }
        }
        __syncthreads();

        // --- O = O*alpha + P @ V (warp 16q x 32d), 4 k-steps of 16 keys ---
        float al0 = arow[q0 + g], al1 = arow[q0 + g + 8];
        #pragma unroll
        for (int nt = 0; nt < 4; nt++) {
            acc_o[nt][0] *= al0; acc_o[nt][1] *= al0;
            acc_o[nt][2] *= al1; acc_o[nt][3] *= al1;
        }
        #pragma unroll
        for (int k0 = 0; k0 < 64; k0 += 16) {
            uint32_t af[4];
            uint2 lo = *(const uint2*)(Ps + (q0 + g) * 72 + k0 + 4 * t);
            uint2 hi = *(const uint2*)(Ps + (q0 + g + 8) * 72 + k0 + 4 * t);
            af[0] = lo.x; af[2] = lo.y; af[1] = hi.x; af[3] = hi.y;
            #pragma unroll
            for (int nt = 0; nt < 4; nt++) {
                uint2 bv = *(const uint2*)(Vt + (n0 + nt * 8 + g) * 72 + k0 + 4 * t);
                uint32_t bf[2] = { bv.x, bv.y };
                mma_f16(acc_o[nt], af, bf);
            }
        }
    }

    // --- finalize: /l, write fp16-perm [B,N,H*HD] ---
    float li0 = 1.f / lrow[q0 + g];
    float li1 = 1.f / lrow[q0 + g + 8];
    int nrow0 = qt * 64 + q0 + g;
    __half* o0 = out + (size_t)(b * SEQ + nrow0) * DIM;
    __half* o1 = out + (size_t)(b * SEQ + nrow0 + 8) * DIM;
    #pragma unroll
    for (int nt = 0; nt < 4; nt++) {
        int col = h * HDIM + n0 + nt * 8 + 2 * t;
        *(__half2*)(o0 + PH(col)) = __floats2half2_rn(acc_o[nt][0] * li0, acc_o[nt][1] * li0);
        *(__half2*)(o1 + PH(col)) = __floats2half2_rn(acc_o[nt][2] * li1, acc_o[nt][3] * li1);
    }
}

// ---------------- launch ----------------
extern "C" void kernel_launch(void* const* d_in, const int* in_sizes, int n_in,
                              void* d_out, int out_size) {
    const float* x      = (const float*)d_in[0];
    const float* prompt = (const float*)d_in[1];
    const float* qkv_w  = (const float*)d_in[2];
    const float* qkv_b  = (const float*)d_in[3];
    const float* out_w  = (const float*)d_in[4];
    const float* out_b  = (const float*)d_in[5];
    const float* ln1_g  = (const float*)d_in[6];
    const float* ln1_b  = (const float*)d_in[7];
    const float* ln2_g  = (const float*)d_in[8];
    const float* ln2_b  = (const float*)d_in[9];
    const float* fc1_w  = (const float*)d_in[10];
    const float* fc1_b  = (const float*)d_in[11];
    const float* fc2_w  = (const float*)d_in[12];
    const float* fc2_b  = (const float*)d_in[13];
    float* out = (float*)d_out;

    __half *h, *qkv, *attn, *ff, *wq, *wo, *wf1, *wf2;
    float *xr;
    cudaGetSymbolAddress((void**)&h,    g_h);
    cudaGetSymbolAddress((void**)&qkv,  g_qkv);
    cudaGetSymbolAddress((void**)&attn, g_attn);
    cudaGetSymbolAddress((void**)&xr,   g_xr);
    cudaGetSymbolAddress((void**)&ff,   g_ff);
    cudaGetSymbolAddress((void**)&wq,   g_wq);
    cudaGetSymbolAddress((void**)&wo,   g_wo);
    cudaGetSymbolAddress((void**)&wf1,  g_wf1);
    cudaGetSymbolAddress((void**)&wf2,  g_wf2);

    cudaFuncSetAttribute(attn_kernel, cudaFuncAttributeMaxDynamicSharedMemorySize, ATT_SMEM_BYTES);
    cudaFuncSetAttribute(mma_gemm, cudaFuncAttributeMaxDynamicSharedMemorySize, GSM_BYTES);

    // 0) weight conversion to fp16-perm
    cvt_w<<<(3 * DIM * DIM + 255) / 256, 256>>>(qkv_w, wq, 3 * DIM * DIM, DIM);
    cvt_w<<<(DIM * DIM + 255) / 256, 256>>>(out_w, wo, DIM * DIM, DIM);
    cvt_w<<<(FFD * DIM + 255) / 256, 256>>>(fc1_w, wf1, FFD * DIM, DIM);
    cvt_w<<<(DIM * FFD + 255) / 256, 256>>>(fc2_w, wf2, DIM * FFD, FFD);

    // 1) h = LN1(x)  (fp16-perm)
    ln_kernel<<<ROWS, 256>>>(x, ln1_g, ln1_b, h);
    // 2) qkv = h @ qkv_w^T + qkv_b  (fp16-perm out)
    mma_gemm<<<dim3(3 * DIM / 128, ROWS / 128), 256, GSM_BYTES>>>(h, wq, qkv_b, nullptr, qkv,
                                                                  ROWS, 3 * DIM, DIM, 0);
    // 3) attention (fp16 tensor-core flash, fp16-perm out)
    attn_kernel<<<dim3(SEQ / 64, NH, BSZ), 256, ATT_SMEM_BYTES>>>(qkv, prompt, attn);
    // 4) xr = x + attn @ out_w^T + out_b  (fp32 out)
    mma_gemm<<<dim3(DIM / 128, ROWS / 128), 256, GSM_BYTES>>>(attn, wo, out_b, x, xr,
                                                              ROWS, DIM, DIM, 2);
    // 5) h = LN2(xr)  (fp16-perm)
    ln_kernel<<<ROWS, 256>>>(xr, ln2_g, ln2_b, h);
    // 6) ff = quickgelu(h @ fc1_w^T + fc1_b)  (fp16-perm out)
    mma_gemm<<<dim3(FFD / 128, ROWS / 128), 256, GSM_BYTES>>>(h, wf1, fc1_b, nullptr, ff,
                                                              ROWS, FFD, DIM, 1);
    // 7) out = xr + ff @ fc2_w^T + fc2_b  (fp32 out)
    mma_gemm<<<dim3(DIM / 128, ROWS / 128), 256, GSM_BYTES>>>(ff, wf2, fc2_b, xr, out,
                                                              ROWS, DIM, FFD, 2);
}

// round 7
// speedup vs baseline: 3.7869x; 1.2692x over previous
#include <cuda_runtime.h>
#include <cuda_fp16.h>
#include <cstdint>

// ---------------- problem constants ----------------
#define BSZ   16
#define SEQ   1024
#define DIM   768
#define NH    12
#define HDIM  64
#define PLEN  16
#define KEYS  (PLEN + SEQ)       // 1040
#define FFD   (4 * DIM)          // 3072
#define ROWS  (BSZ * SEQ)        // 16384

// ---------------- scratch (device globals: no alloc allowed) ----------------
__device__ __half g_h   [(size_t)ROWS * DIM];      // LN out, fp16 row-major
__device__ __half g_qkv [(size_t)ROWS * 3 * DIM];  // qkv fp16
__device__ __half g_attn[(size_t)ROWS * DIM];      // attn out fp16
__device__ float  g_xr  [(size_t)ROWS * DIM];      // residual 1, fp32
__device__ __half g_ff  [(size_t)ROWS * FFD];      // gelu out fp16
__device__ __half g_wq  [(size_t)3 * DIM * DIM];   // weights fp16
__device__ __half g_wo  [(size_t)DIM * DIM];
__device__ __half g_wf1 [(size_t)FFD * DIM];
__device__ __half g_wf2 [(size_t)DIM * FFD];

// ---------------- helpers ----------------
__device__ __forceinline__ uint32_t smem_u32(const void* p) {
    uint32_t a;
    asm("{ .reg .u64 t; cvta.to.shared.u64 t, %1; cvt.u32.u64 %0, t; }" : "=r"(a) : "l"(p));
    return a;
}
__device__ __forceinline__ void cp_async16(uint32_t dst, const void* src) {
    asm volatile("cp.async.cg.shared.global [%0], [%1], 16;" :: "r"(dst), "l"(src) : "memory");
}
#define CP_COMMIT() asm volatile("cp.async.commit_group;" ::: "memory")
#define CP_WAIT(n)  asm volatile("cp.async.wait_group %0;" :: "n"(n) : "memory")

__device__ __forceinline__ void ldsm_x4(uint32_t* r, uint32_t addr) {
    asm volatile("ldmatrix.sync.aligned.m8n8.x4.shared.b16 {%0,%1,%2,%3}, [%4];"
        : "=r"(r[0]), "=r"(r[1]), "=r"(r[2]), "=r"(r[3]) : "r"(addr));
}
__device__ __forceinline__ void ldsm_x4_t(uint32_t* r, uint32_t addr) {
    asm volatile("ldmatrix.sync.aligned.m8n8.x4.trans.shared.b16 {%0,%1,%2,%3}, [%4];"
        : "=r"(r[0]), "=r"(r[1]), "=r"(r[2]), "=r"(r[3]) : "r"(addr));
}
__device__ __forceinline__ void mma_f16(float* c, const uint32_t* a, const uint32_t* b) {
    asm volatile(
        "mma.sync.aligned.m16n8k16.row.col.f32.f16.f16.f32 "
        "{%0,%1,%2,%3}, {%4,%5,%6,%7}, {%8,%9}, {%0,%1,%2,%3};"
        : "+f"(c[0]), "+f"(c[1]), "+f"(c[2]), "+f"(c[3])
        : "r"(a[0]), "r"(a[1]), "r"(a[2]), "r"(a[3]), "r"(b[0]), "r"(b[1]));
}

// ---------------- weight convert: fp32 -> fp16 ----------------
__global__ void cvt_w(const float* __restrict__ in, __half* __restrict__ out, int total) {
    int idx = blockIdx.x * 256 + threadIdx.x;
    if (idx >= total) return;
    out[idx] = __float2half(in[idx]);
}

// ---------------- fp16 mma.sync GEMM, ldmatrix fragments, 3-stage cp.async ----------------
// C = A @ W^T + bias. modes: 0 = fp16 out, 1 = gelu + fp16 out, 2 = resid + fp32 out
// 128x128 CTA tile, 8 warps of 64x32, K-chunks of 64 halves (128B/row), triple buffer.
// smem row stride 144B.
#define GBUFB     18432
#define ABUF(s)   ((s) * GBUFB)
#define BBUF(s)   (3 * GBUFB + (s) * GBUFB)
#define GSM_BYTES (6 * GBUFB)

__global__ void __launch_bounds__(256, 2)
mma_gemm(const __half* __restrict__ A, const __half* __restrict__ W,
         const float* __restrict__ bias, const float* __restrict__ resid,
         void* __restrict__ Cout, int M, int N, int K, int mode) {
    extern __shared__ char smc[];
    uint32_t sb = smem_u32(smc);
    int tid = threadIdx.x;
    int wid = tid >> 5, lane = tid & 31;
    int g = lane >> 2, t = lane & 3;
    int bm = blockIdx.y, bn = blockIdx.x;
    int wm0 = (wid & 1) * 64, wn0 = (wid >> 1) * 32;

    // ldmatrix lane offsets (bytes, within buffer)
    uint32_t a_off = (uint32_t)((wm0 + (lane & 15)) * 144 + ((lane >> 4) * 8) * 2);
    uint32_t b_off = (uint32_t)((wn0 + ((lane >> 4) << 3) + (lane & 7)) * 144 + (((lane >> 3) & 1) * 8) * 2);

    int r  = tid >> 1;
    int hh = (tid & 1) << 5;
    const __half* Ap = A + (size_t)(bm * 128 + r) * K + hh;
    const __half* Wp = W + (size_t)(bn * 128 + r) * K + hh;
    uint32_t smA_dst[3], smB_dst[3];
    #pragma unroll
    for (int s = 0; s < 3; s++) {
        smA_dst[s] = sb + ABUF(s) + r * 144 + hh * 2;
        smB_dst[s] = sb + BBUF(s) + r * 144 + hh * 2;
    }

    float acc[4][4][4] = {};
    int nc = K >> 6;

    #pragma unroll
    for (int i = 0; i < 4; i++) cp_async16(smA_dst[0] + i * 16, Ap + i * 8);
    #pragma unroll
    for (int i = 0; i < 4; i++) cp_async16(smB_dst[0] + i * 16, Wp + i * 8);
    CP_COMMIT();
    #pragma unroll
    for (int i = 0; i < 4; i++) cp_async16(smA_dst[1] + i * 16, Ap + 64 + i * 8);
    #pragma unroll
    for (int i = 0; i < 4; i++) cp_async16(smB_dst[1] + i * 16, Wp + 64 + i * 8);
    CP_COMMIT();

    for (int c = 0; c < nc; c++) {
        int s = c % 3;
        if (c + 2 < nc) {
            int s2 = (c + 2) % 3;
            const __half* ap = Ap + (c + 2) * 64;
            const __half* wp = Wp + (c + 2) * 64;
            #pragma unroll
            for (int i = 0; i < 4; i++) cp_async16(smA_dst[s2] + i * 16, ap + i * 8);
            #pragma unroll
            for (int i = 0; i < 4; i++) cp_async16(smB_dst[s2] + i * 16, wp + i * 8);
            CP_COMMIT();
            CP_WAIT(2);
        } else if (c + 1 < nc) {
            CP_WAIT(1);
        } else {
            CP_WAIT(0);
        }
        __syncthreads();

        uint32_t Ab = sb + ABUF(s) + a_off;
        uint32_t Bb = sb + BBUF(s) + b_off;
        #pragma unroll
        for (int k0 = 0; k0 < 64; k0 += 16) {
            uint32_t af[4][4], bf[2][4];
            #pragma unroll
            for (int mt = 0; mt < 4; mt++) ldsm_x4(af[mt], Ab + mt * 2304 + k0 * 2);
            ldsm_x4(bf[0], Bb + k0 * 2);
            ldsm_x4(bf[1], Bb + 2304 + k0 * 2);
            #pragma unroll
            for (int mt = 0; mt < 4; mt++)
                #pragma unroll
                for (int nt = 0; nt < 4; nt++)
                    mma_f16(acc[mt][nt], af[mt], &bf[nt >> 1][(nt & 1) * 2]);
        }
        __syncthreads();
    }

    // epilogue
    #pragma unroll
    for (int mt = 0; mt < 4; mt++) {
        #pragma unroll
        for (int half_ = 0; half_ < 2; half_++) {
            int row = bm * 128 + wm0 + mt * 16 + g + half_ * 8;
            #pragma unroll
            for (int nt = 0; nt < 4; nt++) {
                int col = bn * 128 + wn0 + nt * 8 + 2 * t;
                float vx = acc[mt][nt][2 * half_ + 0] + bias[col];
                float vy = acc[mt][nt][2 * half_ + 1] + bias[col + 1];
                if (mode == 2) {
                    float2 rs = *(const float2*)(resid + (size_t)row * N + col);
                    vx += rs.x; vy += rs.y;
                    *(float2*)((float*)Cout + (size_t)row * N + col) = make_float2(vx, vy);
                } else {
                    if (mode == 1) {
                        vx *= 1.f / (1.f + __expf(-1.702f * vx));
                        vy *= 1.f / (1.f + __expf(-1.702f * vy));
                    }
                    __half* Co = (__half*)Cout + (size_t)row * N;
                    *(__half2*)(Co + col) = __floats2half2_rn(vx, vy);
                }
            }
        }
    }
}

// ---------------- LayerNorm -> fp16 output ----------------
__global__ void ln_kernel(const float* __restrict__ x, const float* __restrict__ g,
                          const float* __restrict__ b, __half* __restrict__ out) {
    int row = blockIdx.x;
    const float* xr = x + (size_t)row * DIM;
    __half* orow = out + (size_t)row * DIM;
    int tid = threadIdx.x;

    float s = 0.f, ss = 0.f;
    for (int i = tid; i < DIM; i += 256) { float v = xr[i]; s += v; ss += v * v; }
    __shared__ float red0[8], red1[8];
    #pragma unroll
    for (int o = 16; o > 0; o >>= 1) {
        s  += __shfl_xor_sync(0xffffffffu, s, o);
        ss += __shfl_xor_sync(0xffffffffu, ss, o);
    }
    if ((tid & 31) == 0) { red0[tid >> 5] = s; red1[tid >> 5] = ss; }
    __syncthreads();
    float st = 0.f, sst = 0.f;
    #pragma unroll
    for (int i = 0; i < 8; i++) { st += red0[i]; sst += red1[i]; }
    float mean = st * (1.f / DIM);
    float var  = sst * (1.f / DIM) - mean * mean;
    float rstd = rsqrtf(var + 1e-5f);
    for (int i = tid; i < DIM; i += 256)
        orow[i] = __float2half((xr[i] - mean) * rstd * g[i] + b[i]);
}

// ---------------- fused attention: fp16 mma.sync + ldmatrix flash attention ----------------
// 256 threads (8 warps), q-tile 64, key-tiles of 64 (17 iters).
// smem: Qs 64x72h, Ks 64x72h, Vs 64x72h (row-major [key][d]), Sb 64x68 f32, Ps 64x72h, m/l/a
#define AQS 0
#define AKS 2304
#define AVS 4608
#define ASB 6912
#define APS 11264
#define AMR 13568
#define ALR 13632
#define AAR 13696
#define ATT_SMEM_BYTES (13760 * 4)

__global__ void __launch_bounds__(256, 3)
attn_kernel(const __half* __restrict__ qkv, const float* __restrict__ prompt,
            __half* __restrict__ out) {
    extern __shared__ uint32_t su[];
    __half* Qs = (__half*)(su + AQS);
    __half* Ks = (__half*)(su + AKS);
    __half* Vs = (__half*)(su + AVS);
    float*  Sb = (float*)(su + ASB);
    __half* Ps = (__half*)(su + APS);
    float* mrow = (float*)(su + AMR);
    float* lrow = (float*)(su + ALR);
    float* arow = (float*)(su + AAR);

    uint32_t sbase = smem_u32(su);
    int qt = blockIdx.x, h = blockIdx.y, b = blockIdx.z;
    int tid = threadIdx.x;
    int wid = tid >> 5, lane = tid & 31;
    int g = lane >> 2, t = lane & 3;
    int q0 = (wid & 3) * 16;
    int n0 = (wid >> 2) * 32;

    // ldmatrix lane offsets (bytes)
    uint32_t aq_off = (uint32_t)((q0 + (lane & 15)) * 144 + ((lane >> 4) * 8) * 2);
    uint32_t bk_off = (uint32_t)((n0 + ((lane >> 4) << 3) + (lane & 7)) * 144 + (((lane >> 3) & 1) * 8) * 2);
    uint32_t bv_off = (uint32_t)((lane & 15) * 144 + (n0 + ((lane >> 4) << 3)) * 2);

    // --- Q tile: verbatim copy ---
    {
        int q = tid & 63, ch = tid >> 6;
        int n = qt * 64 + q;
        const __half* src = qkv + (size_t)(b * SEQ + n) * (3 * DIM) + h * HDIM + ch * 16;
        *(uint4*)(Qs + q * 72 + ch * 16)     = *(const uint4*)(src);
        *(uint4*)(Qs + q * 72 + ch * 16 + 8) = *(const uint4*)(src + 8);
    }
    if (tid < 64) { mrow[tid] = -1e30f; lrow[tid] = 0.f; }

    float acc_o[4][4] = {};

    for (int kt = 0; kt < 17; kt++) {
        __syncthreads();
        // --- K tile -> Ks[key][d] ---
        {
            int key = tid & 63, ch = tid >> 6;
            int kg = kt * 64 + key;
            if (kg >= KEYS) {
                uint4 z = make_uint4(0, 0, 0, 0);
                *(uint4*)(Ks + key * 72 + ch * 16)     = z;
                *(uint4*)(Ks + key * 72 + ch * 16 + 8) = z;
            } else if (kg >= PLEN) {
                const __half* src = qkv + (size_t)(b * SEQ + (kg - PLEN)) * (3 * DIM)
                                    + DIM + h * HDIM + ch * 16;
                *(uint4*)(Ks + key * 72 + ch * 16)     = *(const uint4*)(src);
                *(uint4*)(Ks + key * 72 + ch * 16 + 8) = *(const uint4*)(src + 8);
            } else {
                const float* src = prompt + ((((size_t)b * 2 + 0) * PLEN + kg) * NH + h) * HDIM + ch * 16;
                #pragma unroll
                for (int ii = 0; ii < 8; ii++) {
                    float2 v = *(const float2*)(src + ii * 2);
                    *(__half2*)(Ks + key * 72 + ch * 16 + ii * 2) = __floats2half2_rn(v.x, v.y);
                }
            }
        }
        // --- V tile -> Vs[key][d] ---
        {
            int key = tid & 63, ch = tid >> 6;
            int kg = kt * 64 + key;
            if (kg >= KEYS) {
                uint4 z = make_uint4(0, 0, 0, 0);
                *(uint4*)(Vs + key * 72 + ch * 16)     = z;
                *(uint4*)(Vs + key * 72 + ch * 16 + 8) = z;
            } else if (kg >= PLEN) {
                const __half* src = qkv + (size_t)(b * SEQ + (kg - PLEN)) * (3 * DIM)
                                    + 2 * DIM + h * HDIM + ch * 16;
                *(uint4*)(Vs + key * 72 + ch * 16)     = *(const uint4*)(src);
                *(uint4*)(Vs + key * 72 + ch * 16 + 8) = *(const uint4*)(src + 8);
            } else {
                const float* src = prompt + ((((size_t)b * 2 + 1) * PLEN + kg) * NH + h) * HDIM + ch * 16;
                #pragma unroll
                for (int ii = 0; ii < 8; ii++) {
                    float2 v = *(const float2*)(src + ii * 2);
                    *(__half2*)(Vs + key * 72 + ch * 16 + ii * 2) = __floats2half2_rn(v.x, v.y);
                }
            }
        }
        __syncthreads();

        // --- S = Q @ K^T (warp 16q x 32key), 4 k-steps ---
        float s4[4][4] = {};
        #pragma unroll
        for (int k0 = 0; k0 < 64; k0 += 16) {
            uint32_t af[4], bf[2][4];
            ldsm_x4(af, sbase + AQS * 4 + aq_off + k0 * 2);
            ldsm_x4(bf[0], sbase + AKS * 4 + bk_off + k0 * 2);
            ldsm_x4(bf[1], sbase + AKS * 4 + bk_off + 2304 + k0 * 2);
            #pragma unroll
            for (int nt = 0; nt < 4; nt++)
                mma_f16(s4[nt], af, &bf[nt >> 1][(nt & 1) * 2]);
        }
        #pragma unroll
        for (int nt = 0; nt < 4; nt++) {
            *(float2*)(Sb + (q0 + g) * 68 + n0 + nt * 8 + 2 * t)     = make_float2(s4[nt][0], s4[nt][1]);
            *(float2*)(Sb + (q0 + g + 8) * 68 + n0 + nt * 8 + 2 * t) = make_float2(s4[nt][2], s4[nt][3]);
        }
        __syncthreads();

        // --- online softmax (scale 0.125 here); P -> fp16 ---
        {
            int q = tid >> 2, part = tid & 3;
            int base = part * 16;
            float vals[16];
            #pragma unroll
            for (int i = 0; i < 16; i++) {
                int kg = kt * 64 + base + i;
                vals[i] = (kg < KEYS) ? Sb[q * 68 + base + i] * 0.125f : -1e30f;
            }
            float mt = -1e30f;
            #pragma unroll
            for (int i = 0; i < 16; i++) mt = fmaxf(mt, vals[i]);
            mt = fmaxf(mt, __shfl_xor_sync(0xffffffffu, mt, 1));
            mt = fmaxf(mt, __shfl_xor_sync(0xffffffffu, mt, 2));
            float mold = mrow[q];
            float mnew = fmaxf(mold, mt);
            float ls = 0.f;
            #pragma unroll
            for (int i = 0; i < 16; i += 2) {
                float p0 = __expf(vals[i] - mnew);
                float p1 = __expf(vals[i + 1] - mnew);
                ls += p0 + p1;
                *(__half2*)(Ps + q * 72 + base + i) = __floats2half2_rn(p0, p1);
            }
            ls += __shfl_xor_sync(0xffffffffu, ls, 1);
            ls += __shfl_xor_sync(0xffffffffu, ls, 2);
            float alpha = __expf(mold - mnew);
            if (part == 0) {
                mrow[q] = mnew;
                lrow[q] = lrow[q] * alpha + ls;
                arow[q] = alpha;
            }
        }
        __syncthreads();

        // --- O = O*alpha + P @ V (warp 16q x 32d), 4 k-steps over keys ---
        float al0 = arow[q0 + g], al1 = arow[q0 + g + 8];
        #pragma unroll
        for (int nt = 0; nt < 4; nt++) {
            acc_o[nt][0] *= al0; acc_o[nt][1] *= al0;
            acc_o[nt][2] *= al1; acc_o[nt][3] *= al1;
        }
        #pragma unroll
        for (int k0 = 0; k0 < 64; k0 += 16) {
            uint32_t af[4], bf[2][4];
            ldsm_x4(af, sbase + APS * 4 + aq_off + k0 * 2);
            ldsm_x4_t(bf[0], sbase + AVS * 4 + bv_off + k0 * 144);
            ldsm_x4_t(bf[1], sbase + AVS * 4 + bv_off + 16 * 2 + k0 * 144);
            #pragma unroll
            for (int nt = 0; nt < 4; nt++)
                mma_f16(acc_o[nt], af, &bf[nt >> 1][(nt & 1) * 2]);
        }
    }

    // --- finalize: /l, write fp16 [B,N,H*HD] ---
    float li0 = 1.f / lrow[q0 + g];
    float li1 = 1.f / lrow[q0 + g + 8];
    int nrow0 = qt * 64 + q0 + g;
    __half* o0 = out + (size_t)(b * SEQ + nrow0) * DIM;
    __half* o1 = out + (size_t)(b * SEQ + nrow0 + 8) * DIM;
    #pragma unroll
    for (int nt = 0; nt < 4; nt++) {
        int col = h * HDIM + n0 + nt * 8 + 2 * t;
        *(__half2*)(o0 + col) = __floats2half2_rn(acc_o[nt][0] * li0, acc_o[nt][1] * li0);
        *(__half2*)(o1 + col) = __floats2half2_rn(acc_o[nt][2] * li1, acc_o[nt][3] * li1);
    }
}

// ---------------- launch ----------------
extern "C" void kernel_launch(void* const* d_in, const int* in_sizes, int n_in,
                              void* d_out, int out_size) {
    const float* x      = (const float*)d_in[0];
    const float* prompt = (const float*)d_in[1];
    const float* qkv_w  = (const float*)d_in[2];
    const float* qkv_b  = (const float*)d_in[3];
    const float* out_w  = (const float*)d_in[4];
    const float* out_b  = (const float*)d_in[5];
    const float* ln1_g  = (const float*)d_in[6];
    const float* ln1_b  = (const float*)d_in[7];
    const float* ln2_g  = (const float*)d_in[8];
    const float* ln2_b  = (const float*)d_in[9];
    const float* fc1_w  = (const float*)d_in[10];
    const float* fc1_b  = (const float*)d_in[11];
    const float* fc2_w  = (const float*)d_in[12];
    const float* fc2_b  = (const float*)d_in[13];
    float* out = (float*)d_out;

    __half *h, *qkv, *attn, *ff, *wq, *wo, *wf1, *wf2;
    float *xr;
    cudaGetSymbolAddress((void**)&h,    g_h);
    cudaGetSymbolAddress((void**)&qkv,  g_qkv);
    cudaGetSymbolAddress((void**)&attn, g_attn);
    cudaGetSymbolAddress((void**)&xr,   g_xr);
    cudaGetSymbolAddress((void**)&ff,   g_ff);
    cudaGetSymbolAddress((void**)&wq,   g_wq);
    cudaGetSymbolAddress((void**)&wo,   g_wo);
    cudaGetSymbolAddress((void**)&wf1,  g_wf1);
    cudaGetSymbolAddress((void**)&wf2,  g_wf2);

    cudaFuncSetAttribute(attn_kernel, cudaFuncAttributeMaxDynamicSharedMemorySize, ATT_SMEM_BYTES);
    cudaFuncSetAttribute(mma_gemm, cudaFuncAttributeMaxDynamicSharedMemorySize, GSM_BYTES);

    // 0) weight conversion to fp16
    cvt_w<<<(3 * DIM * DIM + 255) / 256, 256>>>(qkv_w, wq, 3 * DIM * DIM);
    cvt_w<<<(DIM * DIM + 255) / 256, 256>>>(out_w, wo, DIM * DIM);
    cvt_w<<<(FFD * DIM + 255) / 256, 256>>>(fc1_w, wf1, FFD * DIM);
    cvt_w<<<(DIM * FFD + 255) / 256, 256>>>(fc2_w, wf2, DIM * FFD);

    // 1) h = LN1(x)
    ln_kernel<<<ROWS, 256>>>(x, ln1_g, ln1_b, h);
    // 2) qkv = h @ qkv_w^T + qkv_b
    mma_gemm<<<dim3(3 * DIM / 128, ROWS / 128), 256, GSM_BYTES>>>(h, wq, qkv_b, nullptr, qkv,
                                                                  ROWS, 3 * DIM, DIM, 0);
    // 3) attention
    attn_kernel<<<dim3(SEQ / 64, NH, BSZ), 256, ATT_SMEM_BYTES>>>(qkv, prompt, attn);
    // 4) xr = x + attn @ out_w^T + out_b
    mma_gemm<<<dim3(DIM / 128, ROWS / 128), 256, GSM_BYTES>>>(attn, wo, out_b, x, xr,
                                                              ROWS, DIM, DIM, 2);
    // 5) h = LN2(xr)
    ln_kernel<<<ROWS, 256>>>(xr, ln2_g, ln2_b, h);
    // 6) ff = quickgelu(h @ fc1_w^T + fc1_b)
    mma_gemm<<<dim3(FFD / 128, ROWS / 128), 256, GSM_BYTES>>>(h, wf1, fc1_b, nullptr, ff,
                                                              ROWS, FFD, DIM, 1);
    // 7) out = xr + ff @ fc2_w^T + fc2_b
    mma_gemm<<<dim3(DIM / 128, ROWS / 128), 256, GSM_BYTES>>>(ff, wf2, fc2_b, xr, out,
                                                              ROWS, DIM, FFD, 2);
}